// round 13
// baseline (speedup 1.0000x reference)
#include <cuda_runtime.h>
#include <cstdint>

// Problem constants
#define TT   2048
#define HH   512
#define NB   32
#define II   88
#define TH   (TT*HH)           // per-batch stride in hiddens
#define NTOT (NB*TH)           // one hiddens tensor (33554432)
#define NCTA 128
#define GCTA 16                // CTAs per barrier group
#define KSTEPS 511             // D=4: (2048-4)/4 = 511 steps

// rnn dynamic smem layout (floats)
#define HS_F   (16*HH)                   // 8192 : h_{t-4} for 16 streams
#define XROW   96                        // padded x row (88 used, pad reads ok)
#define XNS    (7*XROW)                  // 672  : per-batch window (7 t-rows)
#define XS_F   (4*XNS)                   // 2688 : one x-window slot (4 batches)
#define SMEM_FLOATS (HS_F + 2*XS_F)
#define SMEM_BYTES  (SMEM_FLOATS*4)      // 54272 B

// Device scratch
__device__ float g_W2[HH * HH];      // W^2
__device__ float g_W3[HH * HH];      // W^3
__device__ float g_W4[HH * HH];      // W^4
__device__ float g_WT[HH * HH];      // W transposed (prologue)
__device__ float g_Wp1[HH * II];     // W   * W_ih
__device__ float g_Wp2[HH * II];     // W^2 * W_ih
__device__ float g_Wp3[HH * II];     // W^3 * W_ih
__device__ float g_b1[HH], g_b2[HH], g_b3[HH];
__device__ unsigned g_flag[NCTA * 32];   // per-CTA step flags, 128B apart

// ---------------- release/acquire helpers ----------------
__device__ __forceinline__ void st_release_gpu(unsigned* p, unsigned v) {
    asm volatile("st.release.gpu.global.u32 [%0], %1;" :: "l"(p), "r"(v) : "memory");
}
__device__ __forceinline__ unsigned ld_acquire_gpu(const unsigned* p) {
    unsigned v;
    asm volatile("ld.acquire.gpu.global.u32 %0, [%1];" : "=r"(v) : "l"(p) : "memory");
    return v;
}
__device__ __forceinline__ void wait_ge(const unsigned* p, unsigned target) {
    while (ld_acquire_gpu(p) < target) { }
}

// ---------------------------------------------------------------------------
// Launch #1: mm0 — blocks [0,64): W2 = W*W rows; blocks [64,128): WT rows.
// ---------------------------------------------------------------------------
__global__ void __launch_bounds__(512, 1) mm0_kernel(const float* __restrict__ W)
{
    if (blockIdx.x < 64) {
        __shared__ float as[8][HH];
        const int r0 = blockIdx.x * 8;
        for (int f = threadIdx.x; f < 8 * HH; f += 512)
            as[f >> 9][f & 511] = W[r0 * HH + f];
        __syncthreads();
        const int c = threadIdx.x;
        float acc[8];
#pragma unroll
        for (int r = 0; r < 8; r++) acc[r] = 0.0f;
#pragma unroll 4
        for (int k = 0; k < HH; k++) {
            const float bv = W[k * HH + c];
#pragma unroll
            for (int r = 0; r < 8; r++) acc[r] += as[r][k] * bv;
        }
#pragma unroll
        for (int r = 0; r < 8; r++) g_W2[(r0 + r) * HH + c] = acc[r];
    } else {
        const int r0 = (blockIdx.x - 64) * 8;
        const int c  = threadIdx.x;
#pragma unroll
        for (int r = 0; r < 8; r++)
            g_WT[c * HH + (r0 + r)] = W[(r0 + r) * HH + c];
    }
}

// ---------------------------------------------------------------------------
// Launch #2: mm1 — y=0: W4 = W2*W2 ; y=1: W3 = W2*W.
// ---------------------------------------------------------------------------
__global__ void __launch_bounds__(512, 1) mm1_kernel(const float* __restrict__ W)
{
    const float* B = (blockIdx.y == 0) ? g_W2 : W;
    float* C = (blockIdx.y == 0) ? g_W4 : g_W3;

    __shared__ float as[8][HH];
    const int r0 = blockIdx.x * 8;
    for (int f = threadIdx.x; f < 8 * HH; f += 512)
        as[f >> 9][f & 511] = g_W2[r0 * HH + f];
    __syncthreads();
    const int c = threadIdx.x;
    float acc[8];
#pragma unroll
    for (int r = 0; r < 8; r++) acc[r] = 0.0f;
#pragma unroll 4
    for (int k = 0; k < HH; k++) {
        const float bv = B[k * HH + c];
#pragma unroll
        for (int r = 0; r < 8; r++) acc[r] += as[r][k] * bv;
    }
#pragma unroll
    for (int r = 0; r < 8; r++) C[(r0 + r) * HH + c] = acc[r];
}

// ---------------------------------------------------------------------------
// Launch #3: projw — y = 0,1,2 -> Wp1 = W*W_ih, Wp2 = W2*W_ih, Wp3 = W3*W_ih.
// ---------------------------------------------------------------------------
__global__ void projw_kernel(const float* __restrict__ W,
                             const float* __restrict__ W_ih,
                             const float* __restrict__ b_ih)
{
    const float* A = (blockIdx.y == 0) ? W : (blockIdx.y == 1) ? g_W2 : g_W3;
    float* dst = (blockIdx.y == 0) ? g_Wp1 : (blockIdx.y == 1) ? g_Wp2 : g_Wp3;
    float* db  = (blockIdx.y == 0) ? g_b1  : (blockIdx.y == 1) ? g_b2  : g_b3;

    __shared__ float ar[HH];
    const int r = blockIdx.x;
    for (int f = threadIdx.x; f < HH; f += 96) ar[f] = A[r * HH + f];
    __syncthreads();
    const int i = threadIdx.x;
    if (i < II) {
        float a[8];
#pragma unroll
        for (int q = 0; q < 8; q++) a[q] = 0.0f;
#pragma unroll 4
        for (int k = 0; k < HH; k += 8) {
#pragma unroll
            for (int q = 0; q < 8; q++)
                a[q] += ar[k + q] * W_ih[(k + q) * II + i];
        }
        dst[r * II + i] = ((a[0]+a[4]) + (a[1]+a[5])) + ((a[2]+a[6]) + (a[3]+a[7]));
    } else if (i == II) {
        float a0 = 0.f, a1 = 0.f, a2 = 0.f, a3 = 0.f;
#pragma unroll 4
        for (int k = 0; k < HH; k += 4) {
            a0 += ar[k + 0] * b_ih[k + 0];
            a1 += ar[k + 1] * b_ih[k + 1];
            a2 += ar[k + 2] * b_ih[k + 2];
            a3 += ar[k + 3] * b_ih[k + 3];
        }
        db[r] = (a0 + a1) + (a2 + a3);
    }
}

// ---------------------------------------------------------------------------
// Launch #4: prologue — h0 = initial + W_ih x_0 + b; h_t = W h_{t-1} +
// W_ih x_{t-1} + b for t = 1..3. One block per batch. Also resets flags.
// 8-accumulator / deep-MLP dot (the 512-col loads are the bottleneck).
// ---------------------------------------------------------------------------
__global__ void __launch_bounds__(512, 1) prologue_kernel(
    const float* __restrict__ x,
    const float* __restrict__ initial,
    const float* __restrict__ W_ih,
    const float* __restrict__ b_ih,
    float* __restrict__ out)
{
    __shared__ float hs[HH];
    __shared__ __align__(16) float xsp[3][II];
    const int n = blockIdx.x, r = threadIdx.x;

    if (blockIdx.x == 0 && threadIdx.x < NCTA) g_flag[threadIdx.x * 32] = 0u;

    for (int f = threadIdx.x; f < 3 * II; f += 512)
        xsp[f / II][f % II] = x[(size_t)n * TT * II + f];
    __syncthreads();

    float wih[II];
#pragma unroll
    for (int i = 0; i < II; i++) wih[i] = W_ih[r * II + i];
    const float b = b_ih[r];

    float d0 = 0.f;
#pragma unroll
    for (int i = 0; i < II; i++) d0 += wih[i] * xsp[0][i];
    float h = initial[n * HH + r] + d0 + b;
    out[(size_t)n * TH + r] = h;

#pragma unroll 1
    for (int t = 1; t <= 3; t++) {
        __syncthreads();
        hs[r] = h;
        __syncthreads();
        float a[8];
#pragma unroll
        for (int q = 0; q < 8; q++) a[q] = 0.0f;
#pragma unroll 2
        for (int k = 0; k < HH; k += 8) {
#pragma unroll
            for (int q = 0; q < 8; q++)
                a[q] += g_WT[(k + q) * HH + r] * hs[k + q];
        }
        float dt = 0.f;
#pragma unroll
        for (int i = 0; i < II; i++) dt += wih[i] * xsp[t - 1][i];
        h = (((a[0]+a[4]) + (a[1]+a[5])) + ((a[2]+a[6]) + (a[3]+a[7]))) + dt + b;
        out[(size_t)n * TH + (size_t)t * HH + r] = h;
    }
}

// ---------------------------------------------------------------------------
// Warp butterfly: after 5 rounds on 64 partials lane L owns indices 2L, 2L+1.
// ---------------------------------------------------------------------------
template <int OFF, int M>
__device__ __forceinline__ void red_round(float* acc, int lane)
{
    const bool up = (lane & OFF) != 0;
#pragma unroll
    for (int i = 0; i < M; i++) {
        float keep = up ? acc[i + M] : acc[i];
        float send = up ? acc[i]     : acc[i + M];
        float recv = __shfl_xor_sync(0xffffffffu, send, OFF);
        acc[i] = keep + recv;
    }
}

// Stage a 7-row x window (4 batches) into an xs slot ([n][7][XROW] layout).
// Rows clamped at 2047 (clamped rows are never consumed).
__device__ __forceinline__ void stage_x(
    float* __restrict__ xs_slot, const float* __restrict__ x,
    int n0, int tbase, int tid)
{
#pragma unroll 1
    for (int f = tid; f < 616; f += 256) {
        const int q = f / 22, v = f - q * 22;
        const int n = q / 7, r = q - n * 7;
        int trow = tbase + r;
        if (trow > TT - 1) trow = TT - 1;
        const float4* src = reinterpret_cast<const float4*>(
            x + ((size_t)(n0 + n) * TT + trow) * II);
        reinterpret_cast<float4*>(xs_slot)[n * (XNS / 4) + r * (XROW / 4) + v] = src[v];
    }
}

// In-window u-GEMM: uacc[r*16+s] = sum over 4 sets x 88 of wp * x, butterfly,
// lane L gets u for outputs 2L, 2L+1 (t' = 4k' + chain, same mapping as main).
// wp in registers (fully unrolled — register-array indices must stay static),
// x via conflict-free LDS.32.
__device__ __forceinline__ void ugemm(
    const float (&wp)[4][12], const float* __restrict__ xs_slot,
    int lane, float btot, float& u0, float& u1)
{
    float acc[64];
#pragma unroll
    for (int i = 0; i < 64; i++) acc[i] = 0.0f;
#pragma unroll
    for (int ss = 0; ss < 4; ss++) {
#pragma unroll
        for (int m = 0; m < 3; m++) {
            float xv[16];
#pragma unroll
            for (int s = 0; s < 16; s++)
                xv[s] = xs_slot[(s >> 2) * XNS + (3 + (s & 3) - ss) * XROW
                                + 32 * m + lane];
#pragma unroll
            for (int r = 0; r < 4; r++)
#pragma unroll
                for (int s = 0; s < 16; s++)
                    acc[r * 16 + s] += wp[r][ss * 3 + m] * xv[s];
        }
    }
    red_round<16, 32>(acc, lane);
    red_round< 8, 16>(acc, lane);
    red_round< 4,  8>(acc, lane);
    red_round< 2,  4>(acc, lane);
    red_round< 1,  2>(acc, lane);
    u0 = acc[0] + btot;
    u1 = acc[1] + btot;
}

// ---------------------------------------------------------------------------
// Launch #5: persistent recurrence, D=4, fused u-production (register-tiled).
// 8 groups x 16 CTAs; group = 16 streams (4 batches x 4 chains).
// CTA = 32 rows x 16 streams, 256 threads; warp = 4 rows x 16 streams x full k.
// Main j-loop kept at unroll 2 so the hot-loop body stays under the 32 KB
// I$ tier (grid=128 < 148: the >32KB body throttle applies).
// ---------------------------------------------------------------------------
__global__ void __launch_bounds__(256, 1) rnn_kernel(
    float* __restrict__ out,
    const float* __restrict__ x,
    const float* __restrict__ W_ih,
    const float* __restrict__ b_ih)
{
    extern __shared__ float sm[];
    float* h_s = sm;                 // HS_F floats
    float* xs  = sm + HS_F;          // 2 slots of XS_F floats

    const int tid  = threadIdx.x;
    const int wid  = tid >> 5;
    const int lane = tid & 31;
    const int bg   = blockIdx.x >> 4;    // group 0..7
    const int rg   = blockIdx.x & 15;    // CTA within group
    const int n0   = bg * 4;

    // Register W4 slice: warp owns 4 rows, lane owns k = lane + 32j
    const int rowbase = rg * 32 + wid * 4;
    float w[4][16];
#pragma unroll
    for (int r = 0; r < 4; r++)
#pragma unroll
        for (int j = 0; j < 16; j++)
            w[r][j] = g_W4[(rowbase + r) * HH + lane + 32 * j];

    // Register projection weights: wp[r][ss*3+m] = Wp_ss[rowbase+r][32m+lane]
    float wp[4][12];
#pragma unroll
    for (int ss = 0; ss < 4; ss++) {
        const float* src = (ss == 0) ? W_ih : (ss == 1) ? g_Wp1
                         : (ss == 2) ? g_Wp2 : g_Wp3;
#pragma unroll
        for (int r = 0; r < 4; r++)
#pragma unroll
            for (int m = 0; m < 3; m++) {
                const int idx = 32 * m + lane;
                wp[r][ss * 3 + m] =
                    (idx < II) ? src[(rowbase + r) * II + idx] : 0.0f;
            }
    }

    // Outputs after butterfly: lane owns indices 2L (row L>>3, stream (2L)&15)
    const int myRow = rowbase + (lane >> 3);
    const int s0    = (2 * lane) & 15;
    const int myN   = n0 + (s0 >> 2);
    const int c0    = s0 & 3;            // even chain; second output = c0+1

    // Staging map (h): 16 threads per stream, 8 float4 each
    const int ss2 = tid >> 4;            // stream 0..15
    const int si  = tid & 15;
    const int sN  = n0 + (ss2 >> 2);
    const int sC  = ss2 & 3;

    unsigned* myFlag = &g_flag[(int)blockIdx.x * 32];
    const unsigned* pollFlag = &g_flag[(bg * GCTA + (tid & 15)) * 32];

    const float btot = __ldg(&b_ih[myRow]) + __ldg(&g_b1[myRow])
                     + __ldg(&g_b2[myRow]) + __ldg(&g_b3[myRow]);

    // ---- preloop: stage x slots 0 (tbase 0) + 1 (tbase 4), stage h (t=sC)
    stage_x(xs,        x, n0, 0, tid);
    stage_x(xs + XS_F, x, n0, 4, tid);
    {
        const float4* src = reinterpret_cast<const float4*>(
            out + (size_t)sN * TH + (size_t)sC * HH);
        float4* dst = reinterpret_cast<float4*>(&h_s[ss2 * HH]);
#pragma unroll
        for (int m = 0; m < 8; m++)
            dst[si + m * 16] = __ldcg(src + si + m * 16);
    }
    __syncthreads();

    // u for k=1 (t' = 4+c0, 5+c0) from slot 0 (tbase 0)
    float uv0, uv1;
    ugemm(wp, xs, lane, btot, uv0, uv1);

#pragma unroll 1
    for (int k = 1; k <= KSTEPS; k++) {
        // ---- 1024 FMA per thread: 4 rows x 16 streams x 16 k-values.
        //      unroll 2 keeps the loop body inside the 32 KB I$ tier.
        {
            float acc[64];
#pragma unroll
            for (int i = 0; i < 64; i++) acc[i] = 0.0f;
#pragma unroll 2
            for (int j = 0; j < 16; j++) {
                const int kq = lane + 32 * j;
                float hv[16];
#pragma unroll
                for (int s = 0; s < 16; s++) hv[s] = h_s[s * HH + kq];
#pragma unroll
                for (int r = 0; r < 4; r++)
#pragma unroll
                    for (int s = 0; s < 16; s++)
                        acc[r * 16 + s] += w[r][j] * hv[s];
            }

            // butterfly 64 -> 2 per lane (indices 2*lane, 2*lane+1)
            red_round<16, 32>(acc, lane);
            red_round< 8, 16>(acc, lane);
            red_round< 4,  8>(acc, lane);
            red_round< 2,  4>(acc, lane);
            red_round< 1,  2>(acc, lane);

            const int t0o = 4 * k + c0;
            const size_t oi0 = (size_t)myN * TH + (size_t)t0o * HH + myRow;
            out[oi0]      = acc[0] + uv0;
            out[oi0 + HH] = acc[1] + uv1;
        }

        if (k == KSTEPS) break;              // no tail work needed

        __syncthreads();                     // all CTA stores issued
        if (tid == 0) st_release_gpu(myFlag, (unsigned)k);

        // ---- barrier window: stage x for iter k+1's u-GEMM, then compute
        //      u for step k+1 (t' = 4(k+1)+c0) from slot staged last iter.
        stage_x(xs + ((k + 1) & 1) * XS_F, x, n0, 4 * (k + 1), tid);
        ugemm(wp, xs + (k & 1) * XS_F, lane, btot, uv0, uv1);

        if (tid < GCTA) wait_ge(pollFlag, (unsigned)k);
        __syncthreads();

        // ---- stage h for k+1: t_prev = 4k + sC (just-written lines: L2 hot)
        {
            const float4* src = reinterpret_cast<const float4*>(
                out + (size_t)sN * TH + (size_t)(4 * k + sC) * HH);
            float4* dst = reinterpret_cast<float4*>(&h_s[ss2 * HH]);
#pragma unroll
            for (int m = 0; m < 8; m++)
                dst[si + m * 16] = __ldcg(src + si + m * 16);
        }
        __syncthreads();
    }
}

// ---------------------------------------------------------------------------
// Launch: inputs in metadata order: x, initial, W_ih, b_ih, W_hh
// 5 kernel launches + 1 D2D memcpy.
// ---------------------------------------------------------------------------
extern "C" void kernel_launch(void* const* d_in, const int* in_sizes, int n_in,
                              void* d_out, int out_size)
{
    const float* x       = (const float*)d_in[0];
    const float* initial = (const float*)d_in[1];
    const float* W_ih    = (const float*)d_in[2];
    const float* b_ih    = (const float*)d_in[3];
    const float* W_hh    = (const float*)d_in[4];
    float* out = (float*)d_out;
    const int dup = (out_size >= 2 * NTOT) ? 1 : 0;

    cudaFuncSetAttribute(rnn_kernel,
                         cudaFuncAttributeMaxDynamicSharedMemorySize, SMEM_BYTES);

    mm0_kernel<<<128, 512>>>(W_hh);                          // #1: W2 + WT
    mm1_kernel<<<dim3(64, 2), 512>>>(W_hh);                  // #2: W4, W3
    projw_kernel<<<dim3(HH, 3), 96>>>(W_hh, W_ih, b_ih);     // #3: Wp1..Wp3
    prologue_kernel<<<NB, 512>>>(x, initial, W_ih, b_ih, out);  // #4: h0..h3
    rnn_kernel<<<NCTA, 256, SMEM_BYTES>>>(out, x, W_ih, b_ih);  // #5: recurrence
    if (dup)
        cudaMemcpyAsync(out + NTOT, out, (size_t)NTOT * sizeof(float),
                        cudaMemcpyDeviceToDevice, 0);        // duplicate tensor
}

// round 14
// speedup vs baseline: 1.0531x; 1.0531x over previous
#include <cuda_runtime.h>
#include <cstdint>

// Problem constants
#define TT   2048
#define HH   512
#define NB   32
#define II   88
#define TH   (TT*HH)           // per-batch stride in hiddens
#define NTOT (NB*TH)           // one hiddens tensor (33554432)
#define NCTA 128
#define GCTA 16                // CTAs per barrier group
#define KSTEPS 511             // D=4: (2048-4)/4 = 511 steps

// rnn dynamic smem layout (floats)
#define HS_F   (16*HH)                   // 8192 : h_{t-4} for 16 streams
#define XROW   96                        // padded x row (88 used, pad reads ok)
#define XNS    (7*XROW)                  // 672  : per-batch window (7 t-rows)
#define XS_F   (4*XNS)                   // 2688 : one x-window slot (4 batches)
#define SMEM_FLOATS (HS_F + 2*XS_F)
#define SMEM_BYTES  (SMEM_FLOATS*4)      // 54272 B

// Device scratch
__device__ float g_W2[HH * HH];      // W^2
__device__ float g_W3[HH * HH];      // W^3
__device__ float g_W4[HH * HH];      // W^4
__device__ float g_WT[HH * HH];      // W transposed (prologue)
__device__ float g_Wp1[HH * II];     // W   * W_ih
__device__ float g_Wp2[HH * II];     // W^2 * W_ih
__device__ float g_Wp3[HH * II];     // W^3 * W_ih
__device__ float g_b1[HH], g_b2[HH], g_b3[HH];
__device__ unsigned g_flag[NCTA * 32];   // per-CTA step flags, 128B apart

// ---------------- release/acquire helpers ----------------
__device__ __forceinline__ void st_release_gpu(unsigned* p, unsigned v) {
    asm volatile("st.release.gpu.global.u32 [%0], %1;" :: "l"(p), "r"(v) : "memory");
}
__device__ __forceinline__ unsigned ld_acquire_gpu(const unsigned* p) {
    unsigned v;
    asm volatile("ld.acquire.gpu.global.u32 %0, [%1];" : "=r"(v) : "l"(p) : "memory");
    return v;
}
__device__ __forceinline__ void wait_ge(const unsigned* p, unsigned target) {
    while (ld_acquire_gpu(p) < target) { }
}

// ---------------------------------------------------------------------------
// Launch #1: mm0 — blocks [0,64): W2 = W*W rows; blocks [64,128): WT rows.
// ---------------------------------------------------------------------------
__global__ void __launch_bounds__(512, 1) mm0_kernel(const float* __restrict__ W)
{
    if (blockIdx.x < 64) {
        __shared__ float as[8][HH];
        const int r0 = blockIdx.x * 8;
        for (int f = threadIdx.x; f < 8 * HH; f += 512)
            as[f >> 9][f & 511] = W[r0 * HH + f];
        __syncthreads();
        const int c = threadIdx.x;
        float acc[8];
#pragma unroll
        for (int r = 0; r < 8; r++) acc[r] = 0.0f;
#pragma unroll 4
        for (int k = 0; k < HH; k++) {
            const float bv = W[k * HH + c];
#pragma unroll
            for (int r = 0; r < 8; r++) acc[r] += as[r][k] * bv;
        }
#pragma unroll
        for (int r = 0; r < 8; r++) g_W2[(r0 + r) * HH + c] = acc[r];
    } else {
        const int r0 = (blockIdx.x - 64) * 8;
        const int c  = threadIdx.x;
#pragma unroll
        for (int r = 0; r < 8; r++)
            g_WT[c * HH + (r0 + r)] = W[(r0 + r) * HH + c];
    }
}

// ---------------------------------------------------------------------------
// Launch #2: mm1 — y=0: W4 = W2*W2 ; y=1: W3 = W2*W.
// ---------------------------------------------------------------------------
__global__ void __launch_bounds__(512, 1) mm1_kernel(const float* __restrict__ W)
{
    const float* B = (blockIdx.y == 0) ? g_W2 : W;
    float* C = (blockIdx.y == 0) ? g_W4 : g_W3;

    __shared__ float as[8][HH];
    const int r0 = blockIdx.x * 8;
    for (int f = threadIdx.x; f < 8 * HH; f += 512)
        as[f >> 9][f & 511] = g_W2[r0 * HH + f];
    __syncthreads();
    const int c = threadIdx.x;
    float acc[8];
#pragma unroll
    for (int r = 0; r < 8; r++) acc[r] = 0.0f;
#pragma unroll 4
    for (int k = 0; k < HH; k++) {
        const float bv = B[k * HH + c];
#pragma unroll
        for (int r = 0; r < 8; r++) acc[r] += as[r][k] * bv;
    }
#pragma unroll
    for (int r = 0; r < 8; r++) C[(r0 + r) * HH + c] = acc[r];
}

// ---------------------------------------------------------------------------
// Launch #3: projw — y = 0,1,2 -> Wp1 = W*W_ih, Wp2 = W2*W_ih, Wp3 = W3*W_ih.
// ---------------------------------------------------------------------------
__global__ void projw_kernel(const float* __restrict__ W,
                             const float* __restrict__ W_ih,
                             const float* __restrict__ b_ih)
{
    const float* A = (blockIdx.y == 0) ? W : (blockIdx.y == 1) ? g_W2 : g_W3;
    float* dst = (blockIdx.y == 0) ? g_Wp1 : (blockIdx.y == 1) ? g_Wp2 : g_Wp3;
    float* db  = (blockIdx.y == 0) ? g_b1  : (blockIdx.y == 1) ? g_b2  : g_b3;

    __shared__ float ar[HH];
    const int r = blockIdx.x;
    for (int f = threadIdx.x; f < HH; f += 96) ar[f] = A[r * HH + f];
    __syncthreads();
    const int i = threadIdx.x;
    if (i < II) {
        float a[8];
#pragma unroll
        for (int q = 0; q < 8; q++) a[q] = 0.0f;
#pragma unroll 4
        for (int k = 0; k < HH; k += 8) {
#pragma unroll
            for (int q = 0; q < 8; q++)
                a[q] += ar[k + q] * W_ih[(k + q) * II + i];
        }
        dst[r * II + i] = ((a[0]+a[4]) + (a[1]+a[5])) + ((a[2]+a[6]) + (a[3]+a[7]));
    } else if (i == II) {
        float a0 = 0.f, a1 = 0.f, a2 = 0.f, a3 = 0.f;
#pragma unroll 4
        for (int k = 0; k < HH; k += 4) {
            a0 += ar[k + 0] * b_ih[k + 0];
            a1 += ar[k + 1] * b_ih[k + 1];
            a2 += ar[k + 2] * b_ih[k + 2];
            a3 += ar[k + 3] * b_ih[k + 3];
        }
        db[r] = (a0 + a1) + (a2 + a3);
    }
}

// ---------------------------------------------------------------------------
// Launch #4: prologue — h0 = initial + W_ih x_0 + b; h_t = W h_{t-1} +
// W_ih x_{t-1} + b for t = 1..3. One block per batch. Also resets flags.
// (R11 form — the R12 variant measured slower.)
// ---------------------------------------------------------------------------
__global__ void __launch_bounds__(512, 1) prologue_kernel(
    const float* __restrict__ x,
    const float* __restrict__ initial,
    const float* __restrict__ W_ih,
    const float* __restrict__ b_ih,
    float* __restrict__ out)
{
    __shared__ float hs[HH];
    __shared__ __align__(16) float xsp[3][II];
    const int n = blockIdx.x, r = threadIdx.x;

    if (blockIdx.x == 0 && threadIdx.x < NCTA) g_flag[threadIdx.x * 32] = 0u;

    for (int f = threadIdx.x; f < 3 * II; f += 512)
        xsp[f / II][f % II] = x[(size_t)n * TT * II + f];
    __syncthreads();

    float wih[II];
#pragma unroll
    for (int i = 0; i < II; i++) wih[i] = W_ih[r * II + i];
    const float b = b_ih[r];

    float d0 = 0.f;
#pragma unroll
    for (int i = 0; i < II; i++) d0 += wih[i] * xsp[0][i];
    float h = initial[n * HH + r] + d0 + b;
    out[(size_t)n * TH + r] = h;

#pragma unroll 1
    for (int t = 1; t <= 3; t++) {
        __syncthreads();
        hs[r] = h;
        __syncthreads();
        float a0 = 0.f, a1 = 0.f, a2 = 0.f, a3 = 0.f;
#pragma unroll 4
        for (int k = 0; k < HH; k += 4) {
            a0 += g_WT[(k + 0) * HH + r] * hs[k + 0];
            a1 += g_WT[(k + 1) * HH + r] * hs[k + 1];
            a2 += g_WT[(k + 2) * HH + r] * hs[k + 2];
            a3 += g_WT[(k + 3) * HH + r] * hs[k + 3];
        }
        float dt = 0.f;
#pragma unroll
        for (int i = 0; i < II; i++) dt += wih[i] * xsp[t - 1][i];
        h = (a0 + a1) + (a2 + a3) + dt + b;
        out[(size_t)n * TH + (size_t)t * HH + r] = h;
    }
}

// ---------------------------------------------------------------------------
// Warp butterfly: after 5 rounds on 64 partials lane L owns indices 2L, 2L+1.
// ---------------------------------------------------------------------------
template <int OFF, int M>
__device__ __forceinline__ void red_round(float* acc, int lane)
{
    const bool up = (lane & OFF) != 0;
#pragma unroll
    for (int i = 0; i < M; i++) {
        float keep = up ? acc[i + M] : acc[i];
        float send = up ? acc[i]     : acc[i + M];
        float recv = __shfl_xor_sync(0xffffffffu, send, OFF);
        acc[i] = keep + recv;
    }
}

// Stage a 7-row x window (4 batches) into an xs slot ([n][7][XROW] layout).
// Rows clamped at 2047 (clamped rows are never consumed).
__device__ __forceinline__ void stage_x(
    float* __restrict__ xs_slot, const float* __restrict__ x,
    int n0, int tbase, int tid)
{
#pragma unroll 1
    for (int f = tid; f < 616; f += 256) {
        const int q = f / 22, v = f - q * 22;
        const int n = q / 7, r = q - n * 7;
        int trow = tbase + r;
        if (trow > TT - 1) trow = TT - 1;
        const float4* src = reinterpret_cast<const float4*>(
            x + ((size_t)(n0 + n) * TT + trow) * II);
        reinterpret_cast<float4*>(xs_slot)[n * (XNS / 4) + r * (XROW / 4) + v] = src[v];
    }
}

// One u-GEMM set (SS compile-time so wp indices stay static — no spills):
// uacc[r*16+s] += wp[r][SS*3+m] * x[n(s)][t'(s)-1-SS][32m+lane]
template <int SS>
__device__ __forceinline__ void ugemm_set(
    float* uacc, const float (&wp)[4][12], const float* __restrict__ xs_slot,
    int lane)
{
#pragma unroll
    for (int m = 0; m < 3; m++) {
        float xv[16];
#pragma unroll
        for (int s = 0; s < 16; s++)
            xv[s] = xs_slot[(s >> 2) * XNS + (3 + (s & 3) - SS) * XROW
                            + 32 * m + lane];
#pragma unroll
        for (int r = 0; r < 4; r++)
#pragma unroll
            for (int s = 0; s < 16; s++)
                uacc[r * 16 + s] += wp[r][SS * 3 + m] * xv[s];
    }
}

__device__ __forceinline__ void ubutterfly(
    float* uacc, int lane, float btot, float& u0, float& u1)
{
    red_round<16, 32>(uacc, lane);
    red_round< 8, 16>(uacc, lane);
    red_round< 4,  8>(uacc, lane);
    red_round< 2,  4>(uacc, lane);
    red_round< 1,  2>(uacc, lane);
    u0 = uacc[0] + btot;
    u1 = uacc[1] + btot;
}

// ---------------------------------------------------------------------------
// Launch #5: persistent recurrence, D=4, fused u-production (register-tiled).
// 8 groups x 16 CTAs; group = 16 streams (4 batches x 4 chains).
// CTA = 32 rows x 16 streams, 256 threads; warp = 4 rows x 16 streams x full k.
// u-GEMM split around the poll: sets {0,1} hide release/skew; sets {2,3}
// hide the post-poll h-stage LDG latency (loads issued, FMAs fill the gap).
// ---------------------------------------------------------------------------
__global__ void __launch_bounds__(256, 1) rnn_kernel(
    float* __restrict__ out,
    const float* __restrict__ x,
    const float* __restrict__ W_ih,
    const float* __restrict__ b_ih)
{
    extern __shared__ float sm[];
    float* h_s = sm;                 // HS_F floats
    float* xs  = sm + HS_F;          // 2 slots of XS_F floats

    const int tid  = threadIdx.x;
    const int wid  = tid >> 5;
    const int lane = tid & 31;
    const int bg   = blockIdx.x >> 4;    // group 0..7
    const int rg   = blockIdx.x & 15;    // CTA within group
    const int n0   = bg * 4;

    // Register W4 slice: warp owns 4 rows, lane owns k = lane + 32j
    const int rowbase = rg * 32 + wid * 4;
    float w[4][16];
#pragma unroll
    for (int r = 0; r < 4; r++)
#pragma unroll
        for (int j = 0; j < 16; j++)
            w[r][j] = g_W4[(rowbase + r) * HH + lane + 32 * j];

    // Register projection weights: wp[r][ss*3+m] = Wp_ss[rowbase+r][32m+lane]
    float wp[4][12];
#pragma unroll
    for (int ss = 0; ss < 4; ss++) {
        const float* src = (ss == 0) ? W_ih : (ss == 1) ? g_Wp1
                         : (ss == 2) ? g_Wp2 : g_Wp3;
#pragma unroll
        for (int r = 0; r < 4; r++)
#pragma unroll
            for (int m = 0; m < 3; m++) {
                const int idx = 32 * m + lane;
                wp[r][ss * 3 + m] =
                    (idx < II) ? src[(rowbase + r) * II + idx] : 0.0f;
            }
    }

    // Outputs after butterfly: lane owns indices 2L (row L>>3, stream (2L)&15)
    const int myRow = rowbase + (lane >> 3);
    const int s0    = (2 * lane) & 15;
    const int myN   = n0 + (s0 >> 2);
    const int c0    = s0 & 3;            // even chain; second output = c0+1

    // Staging map (h): 16 threads per stream, 8 float4 each
    const int ss2 = tid >> 4;            // stream 0..15
    const int si  = tid & 15;
    const int sN  = n0 + (ss2 >> 2);
    const int sC  = ss2 & 3;

    unsigned* myFlag = &g_flag[(int)blockIdx.x * 32];
    const unsigned* pollFlag = &g_flag[(bg * GCTA + (tid & 15)) * 32];

    const float btot = __ldg(&b_ih[myRow]) + __ldg(&g_b1[myRow])
                     + __ldg(&g_b2[myRow]) + __ldg(&g_b3[myRow]);

    // ---- preloop: stage x slots 0 (tbase 0) + 1 (tbase 4), stage h (t=sC)
    stage_x(xs,        x, n0, 0, tid);
    stage_x(xs + XS_F, x, n0, 4, tid);
    {
        const float4* src = reinterpret_cast<const float4*>(
            out + (size_t)sN * TH + (size_t)sC * HH);
        float4* dst = reinterpret_cast<float4*>(&h_s[ss2 * HH]);
#pragma unroll
        for (int m = 0; m < 8; m++)
            dst[si + m * 16] = __ldcg(src + si + m * 16);
    }
    __syncthreads();

    // u for k=1 (t' = 4+c0, 5+c0) from slot 0 (tbase 0)
    float uv0, uv1;
    {
        float uacc[64];
#pragma unroll
        for (int i = 0; i < 64; i++) uacc[i] = 0.0f;
        ugemm_set<0>(uacc, wp, xs, lane);
        ugemm_set<1>(uacc, wp, xs, lane);
        ugemm_set<2>(uacc, wp, xs, lane);
        ugemm_set<3>(uacc, wp, xs, lane);
        ubutterfly(uacc, lane, btot, uv0, uv1);
    }

#pragma unroll 1
    for (int k = 1; k <= KSTEPS; k++) {
        // ---- 1024 FMA per thread: 4 rows x 16 streams x 16 k-values
        {
            float acc[64];
#pragma unroll
            for (int i = 0; i < 64; i++) acc[i] = 0.0f;
#pragma unroll
            for (int j = 0; j < 16; j++) {
                const int kq = lane + 32 * j;
                float hv[16];
#pragma unroll
                for (int s = 0; s < 16; s++) hv[s] = h_s[s * HH + kq];
#pragma unroll
                for (int r = 0; r < 4; r++)
#pragma unroll
                    for (int s = 0; s < 16; s++)
                        acc[r * 16 + s] += w[r][j] * hv[s];
            }

            // butterfly 64 -> 2 per lane (indices 2*lane, 2*lane+1)
            red_round<16, 32>(acc, lane);
            red_round< 8, 16>(acc, lane);
            red_round< 4,  8>(acc, lane);
            red_round< 2,  4>(acc, lane);
            red_round< 1,  2>(acc, lane);

            const int t0o = 4 * k + c0;
            const size_t oi0 = (size_t)myN * TH + (size_t)t0o * HH + myRow;
            out[oi0]      = acc[0] + uv0;
            out[oi0 + HH] = acc[1] + uv1;
        }

        if (k == KSTEPS) break;              // no tail work needed

        __syncthreads();                     // all CTA stores issued
        if (tid == 0) st_release_gpu(myFlag, (unsigned)k);

        // ---- barrier window A: stage x for iter k+1, u sets {0,1}
        float uacc[64];
#pragma unroll
        for (int i = 0; i < 64; i++) uacc[i] = 0.0f;
        const float* xslot = xs + (k & 1) * XS_F;

        stage_x(xs + ((k + 1) & 1) * XS_F, x, n0, 4 * (k + 1), tid);
        ugemm_set<0>(uacc, wp, xslot, lane);
        ugemm_set<1>(uacc, wp, xslot, lane);

        if (tid < GCTA) wait_ge(pollFlag, (unsigned)k);
        __syncthreads();

        // ---- window B: h-stage loads interleaved with u sets {2,3}
        {
            const float4* src = reinterpret_cast<const float4*>(
                out + (size_t)sN * TH + (size_t)(4 * k + sC) * HH);
            float4* dst = reinterpret_cast<float4*>(&h_s[ss2 * HH]);

            float4 t0 = __ldcg(src + si);
            float4 t1 = __ldcg(src + si + 16);
            float4 t2 = __ldcg(src + si + 32);
            float4 t3 = __ldcg(src + si + 48);
            ugemm_set<2>(uacc, wp, xslot, lane);     // hides LDG latency
            dst[si]      = t0;
            dst[si + 16] = t1;
            dst[si + 32] = t2;
            dst[si + 48] = t3;

            float4 t4 = __ldcg(src + si + 64);
            float4 t5 = __ldcg(src + si + 80);
            float4 t6 = __ldcg(src + si + 96);
            float4 t7 = __ldcg(src + si + 112);
            ugemm_set<3>(uacc, wp, xslot, lane);     // hides LDG latency
            dst[si + 64]  = t4;
            dst[si + 80]  = t5;
            dst[si + 96]  = t6;
            dst[si + 112] = t7;
        }
        ubutterfly(uacc, lane, btot, uv0, uv1);
        __syncthreads();
    }
}

// ---------------------------------------------------------------------------
// Launch: inputs in metadata order: x, initial, W_ih, b_ih, W_hh
// 5 kernel launches + 1 D2D memcpy.
// ---------------------------------------------------------------------------
extern "C" void kernel_launch(void* const* d_in, const int* in_sizes, int n_in,
                              void* d_out, int out_size)
{
    const float* x       = (const float*)d_in[0];
    const float* initial = (const float*)d_in[1];
    const float* W_ih    = (const float*)d_in[2];
    const float* b_ih    = (const float*)d_in[3];
    const float* W_hh    = (const float*)d_in[4];
    float* out = (float*)d_out;
    const int dup = (out_size >= 2 * NTOT) ? 1 : 0;

    cudaFuncSetAttribute(rnn_kernel,
                         cudaFuncAttributeMaxDynamicSharedMemorySize, SMEM_BYTES);

    mm0_kernel<<<128, 512>>>(W_hh);                          // #1: W2 + WT
    mm1_kernel<<<dim3(64, 2), 512>>>(W_hh);                  // #2: W4, W3
    projw_kernel<<<dim3(HH, 3), 96>>>(W_hh, W_ih, b_ih);     // #3: Wp1..Wp3
    prologue_kernel<<<NB, 512>>>(x, initial, W_ih, b_ih, out);  // #4: h0..h3
    rnn_kernel<<<NCTA, 256, SMEM_BYTES>>>(out, x, W_ih, b_ih);  // #5: recurrence
    if (dup)
        cudaMemcpyAsync(out + NTOT, out, (size_t)NTOT * sizeof(float),
                        cudaMemcpyDeviceToDevice, 0);        // duplicate tensor
}

// round 15
// speedup vs baseline: 1.1125x; 1.0564x over previous
#include <cuda_runtime.h>
#include <cstdint>

// Problem constants
#define TT   2048
#define HH   512
#define NB   32
#define II   88
#define TH   (TT*HH)           // per-batch stride in hiddens
#define NTOT (NB*TH)           // one hiddens tensor (33554432)
#define NCTA 128
#define GCTA 16                // CTAs per barrier group
#define KSTEPS 511             // D=4: (2048-4)/4 = 511 steps

// rnn dynamic smem layout (floats)
#define HS_F   (16*HH)                   // 8192 : h_{t-4} for 16 streams
#define XROW   96                        // padded x row (88 used, pad reads ok)
#define XNS    (7*XROW)                  // 672  : per-batch window (7 t-rows)
#define XS_F   (4*XNS)                   // 2688 : one x-window slot (4 batches)
#define SMEM_FLOATS (HS_F + 2*XS_F)
#define SMEM_BYTES  (SMEM_FLOATS*4)      // 54272 B

// Device scratch
__device__ float g_W2[HH * HH];      // W^2
__device__ float g_W3[HH * HH];      // W^3
__device__ float g_W4[HH * HH];      // W^4
__device__ float g_WT[HH * HH];      // W transposed (prologue)
__device__ float g_WihT[II * HH];    // W_ih transposed (prologue, coalesced)
__device__ float g_Wp1[HH * II];     // W   * W_ih
__device__ float g_Wp2[HH * II];     // W^2 * W_ih
__device__ float g_Wp3[HH * II];     // W^3 * W_ih
__device__ float g_b1[HH], g_b2[HH], g_b3[HH];
__device__ unsigned g_flag[NCTA * 32];   // per-CTA step flags, 128B apart

// ---------------- release/acquire helpers ----------------
__device__ __forceinline__ void st_release_gpu(unsigned* p, unsigned v) {
    asm volatile("st.release.gpu.global.u32 [%0], %1;" :: "l"(p), "r"(v) : "memory");
}
__device__ __forceinline__ unsigned ld_acquire_gpu(const unsigned* p) {
    unsigned v;
    asm volatile("ld.acquire.gpu.global.u32 %0, [%1];" : "=r"(v) : "l"(p) : "memory");
    return v;
}
__device__ __forceinline__ void wait_ge(const unsigned* p, unsigned target) {
    while (ld_acquire_gpu(p) < target) { }
}

// ---------------------------------------------------------------------------
// Launch #1: mm0 — blocks [0,64): W2 = W*W rows; blocks [64,128): WT rows;
// blocks [128,144): W_ihT (16-way split of the 88x512 transpose).
// ---------------------------------------------------------------------------
__global__ void __launch_bounds__(512, 1) mm0_kernel(const float* __restrict__ W,
                                                     const float* __restrict__ W_ih)
{
    if (blockIdx.x < 64) {
        __shared__ float as[8][HH];
        const int r0 = blockIdx.x * 8;
        for (int f = threadIdx.x; f < 8 * HH; f += 512)
            as[f >> 9][f & 511] = W[r0 * HH + f];
        __syncthreads();
        const int c = threadIdx.x;
        float acc[8];
#pragma unroll
        for (int r = 0; r < 8; r++) acc[r] = 0.0f;
#pragma unroll 4
        for (int k = 0; k < HH; k++) {
            const float bv = W[k * HH + c];
#pragma unroll
            for (int r = 0; r < 8; r++) acc[r] += as[r][k] * bv;
        }
#pragma unroll
        for (int r = 0; r < 8; r++) g_W2[(r0 + r) * HH + c] = acc[r];
    } else if (blockIdx.x < 128) {
        const int r0 = (blockIdx.x - 64) * 8;
        const int c  = threadIdx.x;
#pragma unroll
        for (int r = 0; r < 8; r++)
            g_WT[c * HH + (r0 + r)] = W[(r0 + r) * HH + c];
    } else {
        // W_ihT: 88*512 = 45056 elements; 16 blocks x 2816 each.
        const int b = blockIdx.x - 128;
        for (int f = b * 2816 + threadIdx.x; f < (b + 1) * 2816; f += 512) {
            const int r = f / II, i = f - r * II;
            g_WihT[i * HH + r] = W_ih[f];
        }
    }
}

// ---------------------------------------------------------------------------
// Launch #2: mm1 — y=0: W4 = W2*W2 ; y=1: W3 = W2*W.
// ---------------------------------------------------------------------------
__global__ void __launch_bounds__(512, 1) mm1_kernel(const float* __restrict__ W)
{
    const float* B = (blockIdx.y == 0) ? g_W2 : W;
    float* C = (blockIdx.y == 0) ? g_W4 : g_W3;

    __shared__ float as[8][HH];
    const int r0 = blockIdx.x * 8;
    for (int f = threadIdx.x; f < 8 * HH; f += 512)
        as[f >> 9][f & 511] = g_W2[r0 * HH + f];
    __syncthreads();
    const int c = threadIdx.x;
    float acc[8];
#pragma unroll
    for (int r = 0; r < 8; r++) acc[r] = 0.0f;
#pragma unroll 4
    for (int k = 0; k < HH; k++) {
        const float bv = B[k * HH + c];
#pragma unroll
        for (int r = 0; r < 8; r++) acc[r] += as[r][k] * bv;
    }
#pragma unroll
    for (int r = 0; r < 8; r++) C[(r0 + r) * HH + c] = acc[r];
}

// ---------------------------------------------------------------------------
// Launch #3: projw — y = 0,1,2 -> Wp1 = W*W_ih, Wp2 = W2*W_ih, Wp3 = W3*W_ih.
// ---------------------------------------------------------------------------
__global__ void projw_kernel(const float* __restrict__ W,
                             const float* __restrict__ W_ih,
                             const float* __restrict__ b_ih)
{
    const float* A = (blockIdx.y == 0) ? W : (blockIdx.y == 1) ? g_W2 : g_W3;
    float* dst = (blockIdx.y == 0) ? g_Wp1 : (blockIdx.y == 1) ? g_Wp2 : g_Wp3;
    float* db  = (blockIdx.y == 0) ? g_b1  : (blockIdx.y == 1) ? g_b2  : g_b3;

    __shared__ float ar[HH];
    const int r = blockIdx.x;
    for (int f = threadIdx.x; f < HH; f += 96) ar[f] = A[r * HH + f];
    __syncthreads();
    const int i = threadIdx.x;
    if (i < II) {
        float a[8];
#pragma unroll
        for (int q = 0; q < 8; q++) a[q] = 0.0f;
#pragma unroll 4
        for (int k = 0; k < HH; k += 8) {
#pragma unroll
            for (int q = 0; q < 8; q++)
                a[q] += ar[k + q] * W_ih[(k + q) * II + i];
        }
        dst[r * II + i] = ((a[0]+a[4]) + (a[1]+a[5])) + ((a[2]+a[6]) + (a[3]+a[7]));
    } else if (i == II) {
        float a0 = 0.f, a1 = 0.f, a2 = 0.f, a3 = 0.f;
#pragma unroll 4
        for (int k = 0; k < HH; k += 4) {
            a0 += ar[k + 0] * b_ih[k + 0];
            a1 += ar[k + 1] * b_ih[k + 1];
            a2 += ar[k + 2] * b_ih[k + 2];
            a3 += ar[k + 3] * b_ih[k + 3];
        }
        db[r] = (a0 + a1) + (a2 + a3);
    }
}

// ---------------------------------------------------------------------------
// Launch #4: prologue — h0 = initial + W_ih x_0 + b; h_t = W h_{t-1} +
// W_ih x_{t-1} + b for t = 1..3. One block per batch. Also resets flags.
// W_ih dots read g_WihT (coalesced) instead of per-thread strided rows.
// ---------------------------------------------------------------------------
__global__ void __launch_bounds__(512, 1) prologue_kernel(
    const float* __restrict__ x,
    const float* __restrict__ initial,
    const float* __restrict__ b_ih,
    float* __restrict__ out)
{
    __shared__ float hs[HH];
    __shared__ __align__(16) float xsp[3][II];
    const int n = blockIdx.x, r = threadIdx.x;

    if (blockIdx.x == 0 && threadIdx.x < NCTA) g_flag[threadIdx.x * 32] = 0u;

    for (int f = threadIdx.x; f < 3 * II; f += 512)
        xsp[f / II][f % II] = x[(size_t)n * TT * II + f];
    __syncthreads();

    const float b = b_ih[r];

    float d0 = 0.f;
#pragma unroll 4
    for (int i = 0; i < II; i++) d0 += g_WihT[i * HH + r] * xsp[0][i];
    float h = initial[n * HH + r] + d0 + b;
    out[(size_t)n * TH + r] = h;

#pragma unroll 1
    for (int t = 1; t <= 3; t++) {
        __syncthreads();
        hs[r] = h;
        __syncthreads();
        float a0 = 0.f, a1 = 0.f, a2 = 0.f, a3 = 0.f;
#pragma unroll 4
        for (int k = 0; k < HH; k += 4) {
            a0 += g_WT[(k + 0) * HH + r] * hs[k + 0];
            a1 += g_WT[(k + 1) * HH + r] * hs[k + 1];
            a2 += g_WT[(k + 2) * HH + r] * hs[k + 2];
            a3 += g_WT[(k + 3) * HH + r] * hs[k + 3];
        }
        float dt = 0.f;
#pragma unroll 4
        for (int i = 0; i < II; i++) dt += g_WihT[i * HH + r] * xsp[t - 1][i];
        h = (a0 + a1) + (a2 + a3) + dt + b;
        out[(size_t)n * TH + (size_t)t * HH + r] = h;
    }
}

// ---------------------------------------------------------------------------
// Warp butterfly: after 5 rounds on 64 partials lane L owns indices 2L, 2L+1.
// ---------------------------------------------------------------------------
template <int OFF, int M>
__device__ __forceinline__ void red_round(float* acc, int lane)
{
    const bool up = (lane & OFF) != 0;
#pragma unroll
    for (int i = 0; i < M; i++) {
        float keep = up ? acc[i + M] : acc[i];
        float send = up ? acc[i]     : acc[i + M];
        float recv = __shfl_xor_sync(0xffffffffu, send, OFF);
        acc[i] = keep + recv;
    }
}

// Stage a 7-row x window (4 batches) into an xs slot ([n][7][XROW] layout).
// Rows clamped at 2047 (clamped rows are never consumed).
__device__ __forceinline__ void stage_x(
    float* __restrict__ xs_slot, const float* __restrict__ x,
    int n0, int tbase, int tid)
{
#pragma unroll 1
    for (int f = tid; f < 616; f += 256) {
        const int q = f / 22, v = f - q * 22;
        const int n = q / 7, r = q - n * 7;
        int trow = tbase + r;
        if (trow > TT - 1) trow = TT - 1;
        const float4* src = reinterpret_cast<const float4*>(
            x + ((size_t)(n0 + n) * TT + trow) * II);
        reinterpret_cast<float4*>(xs_slot)[n * (XNS / 4) + r * (XROW / 4) + v] = src[v];
    }
}

// One u-GEMM set (SS compile-time so wp indices stay static — no spills):
// uacc[r*16+s] += wp[r][SS*3+m] * x[n(s)][t'(s)-1-SS][32m+lane]
template <int SS>
__device__ __forceinline__ void ugemm_set(
    float* uacc, const float (&wp)[4][12], const float* __restrict__ xs_slot,
    int lane)
{
#pragma unroll
    for (int m = 0; m < 3; m++) {
        float xv[16];
#pragma unroll
        for (int s = 0; s < 16; s++)
            xv[s] = xs_slot[(s >> 2) * XNS + (3 + (s & 3) - SS) * XROW
                            + 32 * m + lane];
#pragma unroll
        for (int r = 0; r < 4; r++)
#pragma unroll
            for (int s = 0; s < 16; s++)
                uacc[r * 16 + s] += wp[r][SS * 3 + m] * xv[s];
    }
}

__device__ __forceinline__ void ubutterfly(
    float* uacc, int lane, float btot, float& u0, float& u1)
{
    red_round<16, 32>(uacc, lane);
    red_round< 8, 16>(uacc, lane);
    red_round< 4,  8>(uacc, lane);
    red_round< 2,  4>(uacc, lane);
    red_round< 1,  2>(uacc, lane);
    u0 = uacc[0] + btot;
    u1 = uacc[1] + btot;
}

// ---------------------------------------------------------------------------
// Launch #5: persistent recurrence, D=4, fused u-production (register-tiled).
// 8 groups x 16 CTAs; group = 16 streams (4 batches x 4 chains).
// CTA = 32 rows x 16 streams, 256 threads; warp = 4 rows x 16 streams x full k.
// Window A (release->poll): ALL 4 ugemm sets (critical-path work).
// Post-poll: h-stage LDGs issued first; stage_x + u-butterfly execute in the
// LDG latency shadow; then STS + sync.
// ---------------------------------------------------------------------------
__global__ void __launch_bounds__(256, 1) rnn_kernel(
    float* __restrict__ out,
    const float* __restrict__ x,
    const float* __restrict__ W_ih,
    const float* __restrict__ b_ih)
{
    extern __shared__ float sm[];
    float* h_s = sm;                 // HS_F floats
    float* xs  = sm + HS_F;          // 2 slots of XS_F floats

    const int tid  = threadIdx.x;
    const int wid  = tid >> 5;
    const int lane = tid & 31;
    const int bg   = blockIdx.x >> 4;    // group 0..7
    const int rg   = blockIdx.x & 15;    // CTA within group
    const int n0   = bg * 4;

    // Register W4 slice: warp owns 4 rows, lane owns k = lane + 32j
    const int rowbase = rg * 32 + wid * 4;
    float w[4][16];
#pragma unroll
    for (int r = 0; r < 4; r++)
#pragma unroll
        for (int j = 0; j < 16; j++)
            w[r][j] = g_W4[(rowbase + r) * HH + lane + 32 * j];

    // Register projection weights: wp[r][ss*3+m] = Wp_ss[rowbase+r][32m+lane]
    float wp[4][12];
#pragma unroll
    for (int ss = 0; ss < 4; ss++) {
        const float* src = (ss == 0) ? W_ih : (ss == 1) ? g_Wp1
                         : (ss == 2) ? g_Wp2 : g_Wp3;
#pragma unroll
        for (int r = 0; r < 4; r++)
#pragma unroll
            for (int m = 0; m < 3; m++) {
                const int idx = 32 * m + lane;
                wp[r][ss * 3 + m] =
                    (idx < II) ? src[(rowbase + r) * II + idx] : 0.0f;
            }
    }

    // Outputs after butterfly: lane owns indices 2L (row L>>3, stream (2L)&15)
    const int myRow = rowbase + (lane >> 3);
    const int s0    = (2 * lane) & 15;
    const int myN   = n0 + (s0 >> 2);
    const int c0    = s0 & 3;            // even chain; second output = c0+1

    // Staging map (h): 16 threads per stream, 8 float4 each
    const int ss2 = tid >> 4;            // stream 0..15
    const int si  = tid & 15;
    const int sN  = n0 + (ss2 >> 2);
    const int sC  = ss2 & 3;

    unsigned* myFlag = &g_flag[(int)blockIdx.x * 32];
    const unsigned* pollFlag = &g_flag[(bg * GCTA + (tid & 15)) * 32];

    const float btot = __ldg(&b_ih[myRow]) + __ldg(&g_b1[myRow])
                     + __ldg(&g_b2[myRow]) + __ldg(&g_b3[myRow]);

    // ---- preloop: stage x slots 0 (tbase 0) + 1 (tbase 4), stage h (t=sC)
    stage_x(xs,        x, n0, 0, tid);
    stage_x(xs + XS_F, x, n0, 4, tid);
    {
        const float4* src = reinterpret_cast<const float4*>(
            out + (size_t)sN * TH + (size_t)sC * HH);
        float4* dst = reinterpret_cast<float4*>(&h_s[ss2 * HH]);
#pragma unroll
        for (int m = 0; m < 8; m++)
            dst[si + m * 16] = __ldcg(src + si + m * 16);
    }
    __syncthreads();

    // u for k=1 (t' = 4+c0, 5+c0) from slot 0 (tbase 0)
    float uv0, uv1;
    {
        float uacc[64];
#pragma unroll
        for (int i = 0; i < 64; i++) uacc[i] = 0.0f;
        ugemm_set<0>(uacc, wp, xs, lane);
        ugemm_set<1>(uacc, wp, xs, lane);
        ugemm_set<2>(uacc, wp, xs, lane);
        ugemm_set<3>(uacc, wp, xs, lane);
        ubutterfly(uacc, lane, btot, uv0, uv1);
    }

#pragma unroll 1
    for (int k = 1; k <= KSTEPS; k++) {
        // ---- 1024 FMA per thread: 4 rows x 16 streams x 16 k-values
        {
            float acc[64];
#pragma unroll
            for (int i = 0; i < 64; i++) acc[i] = 0.0f;
#pragma unroll
            for (int j = 0; j < 16; j++) {
                const int kq = lane + 32 * j;
                float hv[16];
#pragma unroll
                for (int s = 0; s < 16; s++) hv[s] = h_s[s * HH + kq];
#pragma unroll
                for (int r = 0; r < 4; r++)
#pragma unroll
                    for (int s = 0; s < 16; s++)
                        acc[r * 16 + s] += w[r][j] * hv[s];
            }

            // butterfly 64 -> 2 per lane (indices 2*lane, 2*lane+1)
            red_round<16, 32>(acc, lane);
            red_round< 8, 16>(acc, lane);
            red_round< 4,  8>(acc, lane);
            red_round< 2,  4>(acc, lane);
            red_round< 1,  2>(acc, lane);

            const int t0o = 4 * k + c0;
            const size_t oi0 = (size_t)myN * TH + (size_t)t0o * HH + myRow;
            out[oi0]      = acc[0] + uv0;
            out[oi0 + HH] = acc[1] + uv1;
        }

        if (k == KSTEPS) break;              // no tail work needed

        __syncthreads();                     // all CTA stores issued
        if (tid == 0) st_release_gpu(myFlag, (unsigned)k);

        // ---- window A: ALL 4 u-GEMM sets for step k+1 (critical-path work
        //      that also covers the barrier release/skew)
        float uacc[64];
#pragma unroll
        for (int i = 0; i < 64; i++) uacc[i] = 0.0f;
        const float* xslot = xs + (k & 1) * XS_F;
        ugemm_set<0>(uacc, wp, xslot, lane);
        ugemm_set<1>(uacc, wp, xslot, lane);
        ugemm_set<2>(uacc, wp, xslot, lane);
        ugemm_set<3>(uacc, wp, xslot, lane);

        if (tid < GCTA) wait_ge(pollFlag, (unsigned)k);
        __syncthreads();

        // ---- post-poll: issue h LDGs first; stage_x + u-butterfly run in
        //      the LDG latency shadow; then STS h + sync.
        {
            const float4* src = reinterpret_cast<const float4*>(
                out + (size_t)sN * TH + (size_t)(4 * k + sC) * HH);
            float4* dst = reinterpret_cast<float4*>(&h_s[ss2 * HH]);

            float4 t0 = __ldcg(src + si);
            float4 t1 = __ldcg(src + si + 16);
            float4 t2 = __ldcg(src + si + 32);
            float4 t3 = __ldcg(src + si + 48);
            float4 t4 = __ldcg(src + si + 64);
            float4 t5 = __ldcg(src + si + 80);
            float4 t6 = __ldcg(src + si + 96);
            float4 t7 = __ldcg(src + si + 112);

            stage_x(xs + ((k + 1) & 1) * XS_F, x, n0, 4 * (k + 1), tid);
            ubutterfly(uacc, lane, btot, uv0, uv1);

            dst[si]       = t0;
            dst[si + 16]  = t1;
            dst[si + 32]  = t2;
            dst[si + 48]  = t3;
            dst[si + 64]  = t4;
            dst[si + 80]  = t5;
            dst[si + 96]  = t6;
            dst[si + 112] = t7;
        }
        __syncthreads();
    }
}

// ---------------------------------------------------------------------------
// Launch: inputs in metadata order: x, initial, W_ih, b_ih, W_hh
// 5 kernel launches + 1 D2D memcpy.
// ---------------------------------------------------------------------------
extern "C" void kernel_launch(void* const* d_in, const int* in_sizes, int n_in,
                              void* d_out, int out_size)
{
    const float* x       = (const float*)d_in[0];
    const float* initial = (const float*)d_in[1];
    const float* W_ih    = (const float*)d_in[2];
    const float* b_ih    = (const float*)d_in[3];
    const float* W_hh    = (const float*)d_in[4];
    float* out = (float*)d_out;
    const int dup = (out_size >= 2 * NTOT) ? 1 : 0;

    cudaFuncSetAttribute(rnn_kernel,
                         cudaFuncAttributeMaxDynamicSharedMemorySize, SMEM_BYTES);

    mm0_kernel<<<144, 512>>>(W_hh, W_ih);                    // #1: W2 + WT + W_ihT
    mm1_kernel<<<dim3(64, 2), 512>>>(W_hh);                  // #2: W4, W3
    projw_kernel<<<dim3(HH, 3), 96>>>(W_hh, W_ih, b_ih);     // #3: Wp1..Wp3
    prologue_kernel<<<NB, 512>>>(x, initial, b_ih, out);     // #4: h0..h3
    rnn_kernel<<<NCTA, 256, SMEM_BYTES>>>(out, x, W_ih, b_ih);  // #5: recurrence
    if (dup)
        cudaMemcpyAsync(out + NTOT, out, (size_t)NTOT * sizeof(float),
                        cudaMemcpyDeviceToDevice, 0);        // duplicate tensor
}

// round 16
// speedup vs baseline: 1.1205x; 1.0072x over previous
#include <cuda_runtime.h>
#include <cstdint>

// Problem constants
#define TT   2048
#define HH   512
#define NB   32
#define II   88
#define TH   (TT*HH)           // per-batch stride in hiddens
#define NTOT (NB*TH)           // one hiddens tensor (33554432)
#define NCTA 128
#define GCTA 16                // CTAs per barrier group
#define KSTEPS 511             // D=4: (2048-4)/4 = 511 steps

// rnn dynamic smem layout (floats)
#define HS_F   (16*HH)                   // 8192 : h_{t-4} for 16 streams
#define XROW   96                        // padded x row (88 used, pad reads ok)
#define XNS    (7*XROW)                  // 672  : per-batch window (7 t-rows)
#define XS_F   (4*XNS)                   // 2688 : one x-window slot (4 batches)
#define SMEM_FLOATS (HS_F + 2*XS_F)
#define SMEM_BYTES  (SMEM_FLOATS*4)      // 54272 B

// Device scratch
__device__ float g_W2[HH * HH];      // W^2
__device__ float g_W3[HH * HH];      // W^3
__device__ float g_W4[HH * HH];      // W^4
__device__ float g_WT[HH * HH];      // W transposed (prologue)
__device__ float g_WihT[II * HH];    // W_ih transposed (prologue, coalesced)
__device__ float g_Wp1[HH * II];     // W   * W_ih
__device__ float g_Wp2[HH * II];     // W^2 * W_ih
__device__ float g_Wp3[HH * II];     // W^3 * W_ih
__device__ float g_b1[HH], g_b2[HH], g_b3[HH];
__device__ unsigned g_flag[NCTA * 32];   // per-CTA step flags, 128B apart

// ---------------- release/acquire helpers ----------------
__device__ __forceinline__ void st_release_gpu(unsigned* p, unsigned v) {
    asm volatile("st.release.gpu.global.u32 [%0], %1;" :: "l"(p), "r"(v) : "memory");
}
__device__ __forceinline__ unsigned ld_acquire_gpu(const unsigned* p) {
    unsigned v;
    asm volatile("ld.acquire.gpu.global.u32 %0, [%1];" : "=r"(v) : "l"(p) : "memory");
    return v;
}
__device__ __forceinline__ void wait_ge(const unsigned* p, unsigned target) {
    while (ld_acquire_gpu(p) < target) { }
}

// ---------------------------------------------------------------------------
// Launch #1: mm0 — blocks [0,64): W2 = W*W rows; blocks [64,128): WT rows;
// blocks [128,144): W_ihT (16-way split of the 88x512 transpose).
// ---------------------------------------------------------------------------
__global__ void __launch_bounds__(512, 1) mm0_kernel(const float* __restrict__ W,
                                                     const float* __restrict__ W_ih)
{
    if (blockIdx.x < 64) {
        __shared__ float as[8][HH];
        const int r0 = blockIdx.x * 8;
        for (int f = threadIdx.x; f < 8 * HH; f += 512)
            as[f >> 9][f & 511] = W[r0 * HH + f];
        __syncthreads();
        const int c = threadIdx.x;
        float acc[8];
#pragma unroll
        for (int r = 0; r < 8; r++) acc[r] = 0.0f;
#pragma unroll 4
        for (int k = 0; k < HH; k++) {
            const float bv = W[k * HH + c];
#pragma unroll
            for (int r = 0; r < 8; r++) acc[r] += as[r][k] * bv;
        }
#pragma unroll
        for (int r = 0; r < 8; r++) g_W2[(r0 + r) * HH + c] = acc[r];
    } else if (blockIdx.x < 128) {
        const int r0 = (blockIdx.x - 64) * 8;
        const int c  = threadIdx.x;
#pragma unroll
        for (int r = 0; r < 8; r++)
            g_WT[c * HH + (r0 + r)] = W[(r0 + r) * HH + c];
    } else {
        // W_ihT: 88*512 = 45056 elements; 16 blocks x 2816 each.
        const int b = blockIdx.x - 128;
        for (int f = b * 2816 + threadIdx.x; f < (b + 1) * 2816; f += 512) {
            const int r = f / II, i = f - r * II;
            g_WihT[i * HH + r] = W_ih[f];
        }
    }
}

// ---------------------------------------------------------------------------
// Launch #2: mm1 — y=0: W4 = W2*W2 ; y=1: W3 = W2*W.
// ---------------------------------------------------------------------------
__global__ void __launch_bounds__(512, 1) mm1_kernel(const float* __restrict__ W)
{
    const float* B = (blockIdx.y == 0) ? g_W2 : W;
    float* C = (blockIdx.y == 0) ? g_W4 : g_W3;

    __shared__ float as[8][HH];
    const int r0 = blockIdx.x * 8;
    for (int f = threadIdx.x; f < 8 * HH; f += 512)
        as[f >> 9][f & 511] = g_W2[r0 * HH + f];
    __syncthreads();
    const int c = threadIdx.x;
    float acc[8];
#pragma unroll
    for (int r = 0; r < 8; r++) acc[r] = 0.0f;
#pragma unroll 4
    for (int k = 0; k < HH; k++) {
        const float bv = B[k * HH + c];
#pragma unroll
        for (int r = 0; r < 8; r++) acc[r] += as[r][k] * bv;
    }
#pragma unroll
    for (int r = 0; r < 8; r++) C[(r0 + r) * HH + c] = acc[r];
}

// ---------------------------------------------------------------------------
// Launch #3: projw — y = 0,1,2 -> Wp1 = W*W_ih, Wp2 = W2*W_ih, Wp3 = W3*W_ih.
// ---------------------------------------------------------------------------
__global__ void projw_kernel(const float* __restrict__ W,
                             const float* __restrict__ W_ih,
                             const float* __restrict__ b_ih)
{
    const float* A = (blockIdx.y == 0) ? W : (blockIdx.y == 1) ? g_W2 : g_W3;
    float* dst = (blockIdx.y == 0) ? g_Wp1 : (blockIdx.y == 1) ? g_Wp2 : g_Wp3;
    float* db  = (blockIdx.y == 0) ? g_b1  : (blockIdx.y == 1) ? g_b2  : g_b3;

    __shared__ float ar[HH];
    const int r = blockIdx.x;
    for (int f = threadIdx.x; f < HH; f += 96) ar[f] = A[r * HH + f];
    __syncthreads();
    const int i = threadIdx.x;
    if (i < II) {
        float a[8];
#pragma unroll
        for (int q = 0; q < 8; q++) a[q] = 0.0f;
#pragma unroll 4
        for (int k = 0; k < HH; k += 8) {
#pragma unroll
            for (int q = 0; q < 8; q++)
                a[q] += ar[k + q] * W_ih[(k + q) * II + i];
        }
        dst[r * II + i] = ((a[0]+a[4]) + (a[1]+a[5])) + ((a[2]+a[6]) + (a[3]+a[7]));
    } else if (i == II) {
        float a0 = 0.f, a1 = 0.f, a2 = 0.f, a3 = 0.f;
#pragma unroll 4
        for (int k = 0; k < HH; k += 4) {
            a0 += ar[k + 0] * b_ih[k + 0];
            a1 += ar[k + 1] * b_ih[k + 1];
            a2 += ar[k + 2] * b_ih[k + 2];
            a3 += ar[k + 3] * b_ih[k + 3];
        }
        db[r] = (a0 + a1) + (a2 + a3);
    }
}

// ---------------------------------------------------------------------------
// Launch #4: prologue — h0 = initial + W_ih x_0 + b; h_t = W h_{t-1} +
// W_ih x_{t-1} + b for t = 1..3. One block per batch. Also resets flags.
// W_ih dots read g_WihT (coalesced) instead of per-thread strided rows.
// ---------------------------------------------------------------------------
__global__ void __launch_bounds__(512, 1) prologue_kernel(
    const float* __restrict__ x,
    const float* __restrict__ initial,
    const float* __restrict__ b_ih,
    float* __restrict__ out)
{
    __shared__ float hs[HH];
    __shared__ __align__(16) float xsp[3][II];
    const int n = blockIdx.x, r = threadIdx.x;

    if (blockIdx.x == 0 && threadIdx.x < NCTA) g_flag[threadIdx.x * 32] = 0u;

    for (int f = threadIdx.x; f < 3 * II; f += 512)
        xsp[f / II][f % II] = x[(size_t)n * TT * II + f];
    __syncthreads();

    const float b = b_ih[r];

    float d0 = 0.f;
#pragma unroll 4
    for (int i = 0; i < II; i++) d0 += g_WihT[i * HH + r] * xsp[0][i];
    float h = initial[n * HH + r] + d0 + b;
    out[(size_t)n * TH + r] = h;

#pragma unroll 1
    for (int t = 1; t <= 3; t++) {
        __syncthreads();
        hs[r] = h;
        __syncthreads();
        float a0 = 0.f, a1 = 0.f, a2 = 0.f, a3 = 0.f;
#pragma unroll 4
        for (int k = 0; k < HH; k += 4) {
            a0 += g_WT[(k + 0) * HH + r] * hs[k + 0];
            a1 += g_WT[(k + 1) * HH + r] * hs[k + 1];
            a2 += g_WT[(k + 2) * HH + r] * hs[k + 2];
            a3 += g_WT[(k + 3) * HH + r] * hs[k + 3];
        }
        float dt = 0.f;
#pragma unroll 4
        for (int i = 0; i < II; i++) dt += g_WihT[i * HH + r] * xsp[t - 1][i];
        h = (a0 + a1) + (a2 + a3) + dt + b;
        out[(size_t)n * TH + (size_t)t * HH + r] = h;
    }
}

// ---------------------------------------------------------------------------
// Warp butterfly: after 5 rounds on 64 partials lane L owns indices 2L, 2L+1.
// ---------------------------------------------------------------------------
template <int OFF, int M>
__device__ __forceinline__ void red_round(float* acc, int lane)
{
    const bool up = (lane & OFF) != 0;
#pragma unroll
    for (int i = 0; i < M; i++) {
        float keep = up ? acc[i + M] : acc[i];
        float send = up ? acc[i]     : acc[i + M];
        float recv = __shfl_xor_sync(0xffffffffu, send, OFF);
        acc[i] = keep + recv;
    }
}

// Stage a 7-row x window (4 batches) into an xs slot ([n][7][XROW] layout).
// Rows clamped at 2047 (clamped rows are never consumed).
__device__ __forceinline__ void stage_x(
    float* __restrict__ xs_slot, const float* __restrict__ x,
    int n0, int tbase, int tid)
{
#pragma unroll 1
    for (int f = tid; f < 616; f += 256) {
        const int q = f / 22, v = f - q * 22;
        const int n = q / 7, r = q - n * 7;
        int trow = tbase + r;
        if (trow > TT - 1) trow = TT - 1;
        const float4* src = reinterpret_cast<const float4*>(
            x + ((size_t)(n0 + n) * TT + trow) * II);
        reinterpret_cast<float4*>(xs_slot)[n * (XNS / 4) + r * (XROW / 4) + v] = src[v];
    }
}

// One u-GEMM set (SS compile-time so wp indices stay static — no spills):
// uacc[r*16+s] += wp[r][SS*3+m] * x[n(s)][t'(s)-1-SS][32m+lane]
template <int SS>
__device__ __forceinline__ void ugemm_set(
    float* uacc, const float (&wp)[4][12], const float* __restrict__ xs_slot,
    int lane)
{
#pragma unroll
    for (int m = 0; m < 3; m++) {
        float xv[16];
#pragma unroll
        for (int s = 0; s < 16; s++)
            xv[s] = xs_slot[(s >> 2) * XNS + (3 + (s & 3) - SS) * XROW
                            + 32 * m + lane];
#pragma unroll
        for (int r = 0; r < 4; r++)
#pragma unroll
            for (int s = 0; s < 16; s++)
                uacc[r * 16 + s] += wp[r][SS * 3 + m] * xv[s];
    }
}

__device__ __forceinline__ void ubutterfly(
    float* uacc, int lane, float btot, float& u0, float& u1)
{
    red_round<16, 32>(uacc, lane);
    red_round< 8, 16>(uacc, lane);
    red_round< 4,  8>(uacc, lane);
    red_round< 2,  4>(uacc, lane);
    red_round< 1,  2>(uacc, lane);
    u0 = uacc[0] + btot;
    u1 = uacc[1] + btot;
}

// ---------------------------------------------------------------------------
// Launch #5: persistent recurrence, D=4, fused u-production (register-tiled).
// 8 groups x 16 CTAs; group = 16 streams (4 batches x 4 chains).
// CTA = 32 rows x 16 streams, 256 threads; warp = 4 rows x 16 streams x full k.
// Window A (release->poll): ALL 4 ugemm sets (critical-path work).
// Post-poll: h-stage LDGs issued first; stage_x + u-butterfly execute in the
// LDG latency shadow; then STS + sync.
// ---------------------------------------------------------------------------
__global__ void __launch_bounds__(256, 1) rnn_kernel(
    float* __restrict__ out,
    const float* __restrict__ x,
    const float* __restrict__ W_ih,
    const float* __restrict__ b_ih)
{
    extern __shared__ float sm[];
    float* h_s = sm;                 // HS_F floats
    float* xs  = sm + HS_F;          // 2 slots of XS_F floats

    const int tid  = threadIdx.x;
    const int wid  = tid >> 5;
    const int lane = tid & 31;
    const int bg   = blockIdx.x >> 4;    // group 0..7
    const int rg   = blockIdx.x & 15;    // CTA within group
    const int n0   = bg * 4;

    // Register W4 slice: warp owns 4 rows, lane owns k = lane + 32j
    const int rowbase = rg * 32 + wid * 4;
    float w[4][16];
#pragma unroll
    for (int r = 0; r < 4; r++)
#pragma unroll
        for (int j = 0; j < 16; j++)
            w[r][j] = g_W4[(rowbase + r) * HH + lane + 32 * j];

    // Register projection weights: wp[r][ss*3+m] = Wp_ss[rowbase+r][32m+lane]
    float wp[4][12];
#pragma unroll
    for (int ss = 0; ss < 4; ss++) {
        const float* src = (ss == 0) ? W_ih : (ss == 1) ? g_Wp1
                         : (ss == 2) ? g_Wp2 : g_Wp3;
#pragma unroll
        for (int r = 0; r < 4; r++)
#pragma unroll
            for (int m = 0; m < 3; m++) {
                const int idx = 32 * m + lane;
                wp[r][ss * 3 + m] =
                    (idx < II) ? src[(rowbase + r) * II + idx] : 0.0f;
            }
    }

    // Outputs after butterfly: lane owns indices 2L (row L>>3, stream (2L)&15)
    const int myRow = rowbase + (lane >> 3);
    const int s0    = (2 * lane) & 15;
    const int myN   = n0 + (s0 >> 2);
    const int c0    = s0 & 3;            // even chain; second output = c0+1

    // Staging map (h): 16 threads per stream, 8 float4 each
    const int ss2 = tid >> 4;            // stream 0..15
    const int si  = tid & 15;
    const int sN  = n0 + (ss2 >> 2);
    const int sC  = ss2 & 3;

    unsigned* myFlag = &g_flag[(int)blockIdx.x * 32];
    const unsigned* pollFlag = &g_flag[(bg * GCTA + (tid & 15)) * 32];

    const float btot = __ldg(&b_ih[myRow]) + __ldg(&g_b1[myRow])
                     + __ldg(&g_b2[myRow]) + __ldg(&g_b3[myRow]);

    // ---- preloop: stage x slots 0 (tbase 0) + 1 (tbase 4), stage h (t=sC)
    stage_x(xs,        x, n0, 0, tid);
    stage_x(xs + XS_F, x, n0, 4, tid);
    {
        const float4* src = reinterpret_cast<const float4*>(
            out + (size_t)sN * TH + (size_t)sC * HH);
        float4* dst = reinterpret_cast<float4*>(&h_s[ss2 * HH]);
#pragma unroll
        for (int m = 0; m < 8; m++)
            dst[si + m * 16] = __ldcg(src + si + m * 16);
    }
    __syncthreads();

    // u for k=1 (t' = 4+c0, 5+c0) from slot 0 (tbase 0)
    float uv0, uv1;
    {
        float uacc[64];
#pragma unroll
        for (int i = 0; i < 64; i++) uacc[i] = 0.0f;
        ugemm_set<0>(uacc, wp, xs, lane);
        ugemm_set<1>(uacc, wp, xs, lane);
        ugemm_set<2>(uacc, wp, xs, lane);
        ugemm_set<3>(uacc, wp, xs, lane);
        ubutterfly(uacc, lane, btot, uv0, uv1);
    }

#pragma unroll 1
    for (int k = 1; k <= KSTEPS; k++) {
        // ---- 1024 FMA per thread: 4 rows x 16 streams x 16 k-values
        {
            float acc[64];
#pragma unroll
            for (int i = 0; i < 64; i++) acc[i] = 0.0f;
#pragma unroll
            for (int j = 0; j < 16; j++) {
                const int kq = lane + 32 * j;
                float hv[16];
#pragma unroll
                for (int s = 0; s < 16; s++) hv[s] = h_s[s * HH + kq];
#pragma unroll
                for (int r = 0; r < 4; r++)
#pragma unroll
                    for (int s = 0; s < 16; s++)
                        acc[r * 16 + s] += w[r][j] * hv[s];
            }

            // butterfly 64 -> 2 per lane (indices 2*lane, 2*lane+1)
            red_round<16, 32>(acc, lane);
            red_round< 8, 16>(acc, lane);
            red_round< 4,  8>(acc, lane);
            red_round< 2,  4>(acc, lane);
            red_round< 1,  2>(acc, lane);

            const int t0o = 4 * k + c0;
            const size_t oi0 = (size_t)myN * TH + (size_t)t0o * HH + myRow;
            out[oi0]      = acc[0] + uv0;
            out[oi0 + HH] = acc[1] + uv1;
        }

        if (k == KSTEPS) break;              // no tail work needed

        __syncthreads();                     // all CTA stores issued
        if (tid == 0) st_release_gpu(myFlag, (unsigned)k);

        // ---- window A: ALL 4 u-GEMM sets for step k+1 (critical-path work
        //      that also covers the barrier release/skew)
        float uacc[64];
#pragma unroll
        for (int i = 0; i < 64; i++) uacc[i] = 0.0f;
        const float* xslot = xs + (k & 1) * XS_F;
        ugemm_set<0>(uacc, wp, xslot, lane);
        ugemm_set<1>(uacc, wp, xslot, lane);
        ugemm_set<2>(uacc, wp, xslot, lane);
        ugemm_set<3>(uacc, wp, xslot, lane);

        if (tid < GCTA) wait_ge(pollFlag, (unsigned)k);
        __syncthreads();

        // ---- post-poll: issue h LDGs first; stage_x + u-butterfly run in
        //      the LDG latency shadow; then STS h + sync.
        {
            const float4* src = reinterpret_cast<const float4*>(
                out + (size_t)sN * TH + (size_t)(4 * k + sC) * HH);
            float4* dst = reinterpret_cast<float4*>(&h_s[ss2 * HH]);

            float4 t0 = __ldcg(src + si);
            float4 t1 = __ldcg(src + si + 16);
            float4 t2 = __ldcg(src + si + 32);
            float4 t3 = __ldcg(src + si + 48);
            float4 t4 = __ldcg(src + si + 64);
            float4 t5 = __ldcg(src + si + 80);
            float4 t6 = __ldcg(src + si + 96);
            float4 t7 = __ldcg(src + si + 112);

            stage_x(xs + ((k + 1) & 1) * XS_F, x, n0, 4 * (k + 1), tid);
            ubutterfly(uacc, lane, btot, uv0, uv1);

            dst[si]       = t0;
            dst[si + 16]  = t1;
            dst[si + 32]  = t2;
            dst[si + 48]  = t3;
            dst[si + 64]  = t4;
            dst[si + 80]  = t5;
            dst[si + 96]  = t6;
            dst[si + 112] = t7;
        }
        __syncthreads();
    }
}

// ---------------------------------------------------------------------------
// Launch: inputs in metadata order: x, initial, W_ih, b_ih, W_hh
// 5 kernel launches + 1 D2D memcpy.
// ---------------------------------------------------------------------------
extern "C" void kernel_launch(void* const* d_in, const int* in_sizes, int n_in,
                              void* d_out, int out_size)
{
    const float* x       = (const float*)d_in[0];
    const float* initial = (const float*)d_in[1];
    const float* W_ih    = (const float*)d_in[2];
    const float* b_ih    = (const float*)d_in[3];
    const float* W_hh    = (const float*)d_in[4];
    float* out = (float*)d_out;
    const int dup = (out_size >= 2 * NTOT) ? 1 : 0;

    cudaFuncSetAttribute(rnn_kernel,
                         cudaFuncAttributeMaxDynamicSharedMemorySize, SMEM_BYTES);

    mm0_kernel<<<144, 512>>>(W_hh, W_ih);                    // #1: W2 + WT + W_ihT
    mm1_kernel<<<dim3(64, 2), 512>>>(W_hh);                  // #2: W4, W3
    projw_kernel<<<dim3(HH, 3), 96>>>(W_hh, W_ih, b_ih);     // #3: Wp1..Wp3
    prologue_kernel<<<NB, 512>>>(x, initial, b_ih, out);     // #4: h0..h3
    rnn_kernel<<<NCTA, 256, SMEM_BYTES>>>(out, x, W_ih, b_ih);  // #5: recurrence
    if (dup)
        cudaMemcpyAsync(out + NTOT, out, (size_t)NTOT * sizeof(float),
                        cudaMemcpyDeviceToDevice, 0);        // duplicate tensor
}

// round 17
// speedup vs baseline: 1.1467x; 1.0235x over previous
#include <cuda_runtime.h>
#include <cstdint>

// Problem constants
#define TT   2048
#define HH   512
#define NB   32
#define II   88
#define TH   (TT*HH)           // per-batch stride in hiddens
#define NTOT (NB*TH)           // one hiddens tensor (33554432)
#define NCTA 128
#define GCTA 16                // CTAs per barrier group
#define KSTEPS 511             // D=4: (2048-4)/4 = 511 steps

// rnn dynamic smem layout (floats)
#define HS_F   (16*HH)                   // 8192 : h_{t-4} for 16 streams
#define XROW   96                        // padded x row (88 used, pad reads ok)
#define XNS    (7*XROW)                  // 672  : per-batch window (7 t-rows)
#define XS_F   (4*XNS)                   // 2688 : one x-window slot (4 batches)
#define SMEM_FLOATS (HS_F + 2*XS_F)
#define SMEM_BYTES  (SMEM_FLOATS*4)      // 54272 B

// Device scratch
__device__ float g_W2[HH * HH];      // W^2
__device__ float g_W3[HH * HH];      // W^3
__device__ float g_W4[HH * HH];      // W^4
__device__ float g_WT[HH * HH];      // W transposed (prologue)
__device__ float g_Wp1[HH * II];     // W   * W_ih
__device__ float g_Wp2[HH * II];     // W^2 * W_ih
__device__ float g_Wp3[HH * II];     // W^3 * W_ih
__device__ float g_b1[HH], g_b2[HH], g_b3[HH];
__device__ unsigned g_flag[NCTA * 32];   // per-CTA step flags, 128B apart

// ---------------- release/acquire helpers ----------------
__device__ __forceinline__ void st_release_gpu(unsigned* p, unsigned v) {
    asm volatile("st.release.gpu.global.u32 [%0], %1;" :: "l"(p), "r"(v) : "memory");
}
__device__ __forceinline__ unsigned ld_acquire_gpu(const unsigned* p) {
    unsigned v;
    asm volatile("ld.acquire.gpu.global.u32 %0, [%1];" : "=r"(v) : "l"(p) : "memory");
    return v;
}
__device__ __forceinline__ void wait_ge(const unsigned* p, unsigned target) {
    while (ld_acquire_gpu(p) < target) { }
}

// ---------------------------------------------------------------------------
// Launch #1: mm0 — blocks [0,64): W2 = W*W rows; blocks [64,128): WT rows.
// ---------------------------------------------------------------------------
__global__ void __launch_bounds__(512, 1) mm0_kernel(const float* __restrict__ W)
{
    if (blockIdx.x < 64) {
        __shared__ float as[8][HH];
        const int r0 = blockIdx.x * 8;
        for (int f = threadIdx.x; f < 8 * HH; f += 512)
            as[f >> 9][f & 511] = W[r0 * HH + f];
        __syncthreads();
        const int c = threadIdx.x;
        float acc[8];
#pragma unroll
        for (int r = 0; r < 8; r++) acc[r] = 0.0f;
#pragma unroll 4
        for (int k = 0; k < HH; k++) {
            const float bv = W[k * HH + c];
#pragma unroll
            for (int r = 0; r < 8; r++) acc[r] += as[r][k] * bv;
        }
#pragma unroll
        for (int r = 0; r < 8; r++) g_W2[(r0 + r) * HH + c] = acc[r];
    } else {
        const int r0 = (blockIdx.x - 64) * 8;
        const int c  = threadIdx.x;
#pragma unroll
        for (int r = 0; r < 8; r++)
            g_WT[c * HH + (r0 + r)] = W[(r0 + r) * HH + c];
    }
}

// ---------------------------------------------------------------------------
// Launch #2: mm1 — y=0: W4 = W2*W2 ; y=1: W3 = W2*W.
// ---------------------------------------------------------------------------
__global__ void __launch_bounds__(512, 1) mm1_kernel(const float* __restrict__ W)
{
    const float* B = (blockIdx.y == 0) ? g_W2 : W;
    float* C = (blockIdx.y == 0) ? g_W4 : g_W3;

    __shared__ float as[8][HH];
    const int r0 = blockIdx.x * 8;
    for (int f = threadIdx.x; f < 8 * HH; f += 512)
        as[f >> 9][f & 511] = g_W2[r0 * HH + f];
    __syncthreads();
    const int c = threadIdx.x;
    float acc[8];
#pragma unroll
    for (int r = 0; r < 8; r++) acc[r] = 0.0f;
#pragma unroll 4
    for (int k = 0; k < HH; k++) {
        const float bv = B[k * HH + c];
#pragma unroll
        for (int r = 0; r < 8; r++) acc[r] += as[r][k] * bv;
    }
#pragma unroll
    for (int r = 0; r < 8; r++) C[(r0 + r) * HH + c] = acc[r];
}

// ---------------------------------------------------------------------------
// Launch #3: projw — y = 0,1,2 -> Wp1 = W*W_ih, Wp2 = W2*W_ih, Wp3 = W3*W_ih.
// ---------------------------------------------------------------------------
__global__ void projw_kernel(const float* __restrict__ W,
                             const float* __restrict__ W_ih,
                             const float* __restrict__ b_ih)
{
    const float* A = (blockIdx.y == 0) ? W : (blockIdx.y == 1) ? g_W2 : g_W3;
    float* dst = (blockIdx.y == 0) ? g_Wp1 : (blockIdx.y == 1) ? g_Wp2 : g_Wp3;
    float* db  = (blockIdx.y == 0) ? g_b1  : (blockIdx.y == 1) ? g_b2  : g_b3;

    __shared__ float ar[HH];
    const int r = blockIdx.x;
    for (int f = threadIdx.x; f < HH; f += 96) ar[f] = A[r * HH + f];
    __syncthreads();
    const int i = threadIdx.x;
    if (i < II) {
        float a[8];
#pragma unroll
        for (int q = 0; q < 8; q++) a[q] = 0.0f;
#pragma unroll 4
        for (int k = 0; k < HH; k += 8) {
#pragma unroll
            for (int q = 0; q < 8; q++)
                a[q] += ar[k + q] * W_ih[(k + q) * II + i];
        }
        dst[r * II + i] = ((a[0]+a[4]) + (a[1]+a[5])) + ((a[2]+a[6]) + (a[3]+a[7]));
    } else if (i == II) {
        float a0 = 0.f, a1 = 0.f, a2 = 0.f, a3 = 0.f;
#pragma unroll 4
        for (int k = 0; k < HH; k += 4) {
            a0 += ar[k + 0] * b_ih[k + 0];
            a1 += ar[k + 1] * b_ih[k + 1];
            a2 += ar[k + 2] * b_ih[k + 2];
            a3 += ar[k + 3] * b_ih[k + 3];
        }
        db[r] = (a0 + a1) + (a2 + a3);
    }
}

// ---------------------------------------------------------------------------
// Launch #4: prologue — h0 = initial + W_ih x_0 + b; h_t = W h_{t-1} +
// W_ih x_{t-1} + b for t = 1..3. One block per batch. Also resets flags.
// (R11 form — both attempted "improvements" measured slower.)
// ---------------------------------------------------------------------------
__global__ void __launch_bounds__(512, 1) prologue_kernel(
    const float* __restrict__ x,
    const float* __restrict__ initial,
    const float* __restrict__ W_ih,
    const float* __restrict__ b_ih,
    float* __restrict__ out)
{
    __shared__ float hs[HH];
    __shared__ __align__(16) float xsp[3][II];
    const int n = blockIdx.x, r = threadIdx.x;

    if (blockIdx.x == 0 && threadIdx.x < NCTA) g_flag[threadIdx.x * 32] = 0u;

    for (int f = threadIdx.x; f < 3 * II; f += 512)
        xsp[f / II][f % II] = x[(size_t)n * TT * II + f];
    __syncthreads();

    float wih[II];
#pragma unroll
    for (int i = 0; i < II; i++) wih[i] = W_ih[r * II + i];
    const float b = b_ih[r];

    float d0 = 0.f;
#pragma unroll
    for (int i = 0; i < II; i++) d0 += wih[i] * xsp[0][i];
    float h = initial[n * HH + r] + d0 + b;
    out[(size_t)n * TH + r] = h;

#pragma unroll 1
    for (int t = 1; t <= 3; t++) {
        __syncthreads();
        hs[r] = h;
        __syncthreads();
        float a0 = 0.f, a1 = 0.f, a2 = 0.f, a3 = 0.f;
#pragma unroll 4
        for (int k = 0; k < HH; k += 4) {
            a0 += g_WT[(k + 0) * HH + r] * hs[k + 0];
            a1 += g_WT[(k + 1) * HH + r] * hs[k + 1];
            a2 += g_WT[(k + 2) * HH + r] * hs[k + 2];
            a3 += g_WT[(k + 3) * HH + r] * hs[k + 3];
        }
        float dt = 0.f;
#pragma unroll
        for (int i = 0; i < II; i++) dt += wih[i] * xsp[t - 1][i];
        h = (a0 + a1) + (a2 + a3) + dt + b;
        out[(size_t)n * TH + (size_t)t * HH + r] = h;
    }
}

// ---------------------------------------------------------------------------
// Warp butterfly: after 5 rounds on 64 partials lane L owns indices 2L, 2L+1.
// ---------------------------------------------------------------------------
template <int OFF, int M>
__device__ __forceinline__ void red_round(float* acc, int lane)
{
    const bool up = (lane & OFF) != 0;
#pragma unroll
    for (int i = 0; i < M; i++) {
        float keep = up ? acc[i + M] : acc[i];
        float send = up ? acc[i]     : acc[i + M];
        float recv = __shfl_xor_sync(0xffffffffu, send, OFF);
        acc[i] = keep + recv;
    }
}

// Stage a 7-row x window (4 batches) into an xs slot ([n][7][XROW] layout).
// Rows clamped at 2047 (clamped rows are never consumed).
__device__ __forceinline__ void stage_x(
    float* __restrict__ xs_slot, const float* __restrict__ x,
    int n0, int tbase, int tid)
{
#pragma unroll 1
    for (int f = tid; f < 616; f += 256) {
        const int q = f / 22, v = f - q * 22;
        const int n = q / 7, r = q - n * 7;
        int trow = tbase + r;
        if (trow > TT - 1) trow = TT - 1;
        const float4* src = reinterpret_cast<const float4*>(
            x + ((size_t)(n0 + n) * TT + trow) * II);
        reinterpret_cast<float4*>(xs_slot)[n * (XNS / 4) + r * (XROW / 4) + v] = src[v];
    }
}

// One u-GEMM set (SS compile-time so wp indices stay static — no spills):
// uacc[r*16+s] += wp[r][SS*3+m] * x[n(s)][t'(s)-1-SS][32m+lane]
template <int SS>
__device__ __forceinline__ void ugemm_set(
    float* uacc, const float (&wp)[4][12], const float* __restrict__ xs_slot,
    int lane)
{
#pragma unroll
    for (int m = 0; m < 3; m++) {
        float xv[16];
#pragma unroll
        for (int s = 0; s < 16; s++)
            xv[s] = xs_slot[(s >> 2) * XNS + (3 + (s & 3) - SS) * XROW
                            + 32 * m + lane];
#pragma unroll
        for (int r = 0; r < 4; r++)
#pragma unroll
            for (int s = 0; s < 16; s++)
                uacc[r * 16 + s] += wp[r][SS * 3 + m] * xv[s];
    }
}

__device__ __forceinline__ void ubutterfly(
    float* uacc, int lane, float btot, float& u0, float& u1)
{
    red_round<16, 32>(uacc, lane);
    red_round< 8, 16>(uacc, lane);
    red_round< 4,  8>(uacc, lane);
    red_round< 2,  4>(uacc, lane);
    red_round< 1,  2>(uacc, lane);
    u0 = uacc[0] + btot;
    u1 = uacc[1] + btot;
}

// ---------------------------------------------------------------------------
// Launch #5: persistent recurrence, D=4, fused u-production (register-tiled).
// 8 groups x 16 CTAs; group = 16 streams (4 batches x 4 chains).
// CTA = 32 rows x 16 streams, 256 threads; warp = 4 rows x 16 streams x full k.
// Main GEMM k-ownership: lane owns k = 4*lane + 128*jj + e (e=0..3) so the
// 16 h values per (jj,stream) are ONE LDS.128 — shared-load instruction count
// in the hot GEMM drops 256 -> 64 per thread per step (conflict-free).
// ---------------------------------------------------------------------------
__global__ void __launch_bounds__(256, 1) rnn_kernel(
    float* __restrict__ out,
    const float* __restrict__ x,
    const float* __restrict__ W_ih,
    const float* __restrict__ b_ih)
{
    extern __shared__ float sm[];
    float* h_s = sm;                 // HS_F floats
    float* xs  = sm + HS_F;          // 2 slots of XS_F floats

    const int tid  = threadIdx.x;
    const int wid  = tid >> 5;
    const int lane = tid & 31;
    const int bg   = blockIdx.x >> 4;    // group 0..7
    const int rg   = blockIdx.x & 15;    // CTA within group
    const int n0   = bg * 4;

    // Register W4 slice: warp owns 4 rows; lane owns k = 4*lane + 128*jj + e
    const int rowbase = rg * 32 + wid * 4;
    float w[4][16];
#pragma unroll
    for (int r = 0; r < 4; r++)
#pragma unroll
        for (int jj = 0; jj < 4; jj++)
#pragma unroll
            for (int e = 0; e < 4; e++)
                w[r][jj * 4 + e] =
                    g_W4[(rowbase + r) * HH + 4 * lane + 128 * jj + e];

    // Register projection weights: wp[r][ss*3+m] = Wp_ss[rowbase+r][32m+lane]
    float wp[4][12];
#pragma unroll
    for (int ss = 0; ss < 4; ss++) {
        const float* src = (ss == 0) ? W_ih : (ss == 1) ? g_Wp1
                         : (ss == 2) ? g_Wp2 : g_Wp3;
#pragma unroll
        for (int r = 0; r < 4; r++)
#pragma unroll
            for (int m = 0; m < 3; m++) {
                const int idx = 32 * m + lane;
                wp[r][ss * 3 + m] =
                    (idx < II) ? src[(rowbase + r) * II + idx] : 0.0f;
            }
    }

    // Outputs after butterfly: lane owns indices 2L (row L>>3, stream (2L)&15)
    const int myRow = rowbase + (lane >> 3);
    const int s0    = (2 * lane) & 15;
    const int myN   = n0 + (s0 >> 2);
    const int c0    = s0 & 3;            // even chain; second output = c0+1

    // Staging map (h): 16 threads per stream, 8 float4 each
    const int ss2 = tid >> 4;            // stream 0..15
    const int si  = tid & 15;
    const int sN  = n0 + (ss2 >> 2);
    const int sC  = ss2 & 3;

    unsigned* myFlag = &g_flag[(int)blockIdx.x * 32];
    const unsigned* pollFlag = &g_flag[(bg * GCTA + (tid & 15)) * 32];

    const float btot = __ldg(&b_ih[myRow]) + __ldg(&g_b1[myRow])
                     + __ldg(&g_b2[myRow]) + __ldg(&g_b3[myRow]);

    // ---- preloop: stage x slots 0 (tbase 0) + 1 (tbase 4), stage h (t=sC)
    stage_x(xs,        x, n0, 0, tid);
    stage_x(xs + XS_F, x, n0, 4, tid);
    {
        const float4* src = reinterpret_cast<const float4*>(
            out + (size_t)sN * TH + (size_t)sC * HH);
        float4* dst = reinterpret_cast<float4*>(&h_s[ss2 * HH]);
#pragma unroll
        for (int m = 0; m < 8; m++)
            dst[si + m * 16] = __ldcg(src + si + m * 16);
    }
    __syncthreads();

    // u for k=1 (t' = 4+c0, 5+c0) from slot 0 (tbase 0)
    float uv0, uv1;
    {
        float uacc[64];
#pragma unroll
        for (int i = 0; i < 64; i++) uacc[i] = 0.0f;
        ugemm_set<0>(uacc, wp, xs, lane);
        ugemm_set<1>(uacc, wp, xs, lane);
        ugemm_set<2>(uacc, wp, xs, lane);
        ugemm_set<3>(uacc, wp, xs, lane);
        ubutterfly(uacc, lane, btot, uv0, uv1);
    }

#pragma unroll 1
    for (int k = 1; k <= KSTEPS; k++) {
        // ---- 1024 FMA per thread, h via LDS.128 (4 streams staged per chunk)
        {
            float acc[64];
#pragma unroll
            for (int i = 0; i < 64; i++) acc[i] = 0.0f;
#pragma unroll
            for (int jj = 0; jj < 4; jj++) {
                const int kq = 4 * lane + 128 * jj;
#pragma unroll
                for (int sc = 0; sc < 4; sc++) {
                    float4 h0 = *reinterpret_cast<const float4*>(
                        &h_s[(sc * 4 + 0) * HH + kq]);
                    float4 h1 = *reinterpret_cast<const float4*>(
                        &h_s[(sc * 4 + 1) * HH + kq]);
                    float4 h2 = *reinterpret_cast<const float4*>(
                        &h_s[(sc * 4 + 2) * HH + kq]);
                    float4 h3 = *reinterpret_cast<const float4*>(
                        &h_s[(sc * 4 + 3) * HH + kq]);
#pragma unroll
                    for (int r = 0; r < 4; r++) {
                        acc[r * 16 + sc * 4 + 0] += w[r][jj * 4 + 0] * h0.x;
                        acc[r * 16 + sc * 4 + 0] += w[r][jj * 4 + 1] * h0.y;
                        acc[r * 16 + sc * 4 + 0] += w[r][jj * 4 + 2] * h0.z;
                        acc[r * 16 + sc * 4 + 0] += w[r][jj * 4 + 3] * h0.w;
                        acc[r * 16 + sc * 4 + 1] += w[r][jj * 4 + 0] * h1.x;
                        acc[r * 16 + sc * 4 + 1] += w[r][jj * 4 + 1] * h1.y;
                        acc[r * 16 + sc * 4 + 1] += w[r][jj * 4 + 2] * h1.z;
                        acc[r * 16 + sc * 4 + 1] += w[r][jj * 4 + 3] * h1.w;
                        acc[r * 16 + sc * 4 + 2] += w[r][jj * 4 + 0] * h2.x;
                        acc[r * 16 + sc * 4 + 2] += w[r][jj * 4 + 1] * h2.y;
                        acc[r * 16 + sc * 4 + 2] += w[r][jj * 4 + 2] * h2.z;
                        acc[r * 16 + sc * 4 + 2] += w[r][jj * 4 + 3] * h2.w;
                        acc[r * 16 + sc * 4 + 3] += w[r][jj * 4 + 0] * h3.x;
                        acc[r * 16 + sc * 4 + 3] += w[r][jj * 4 + 1] * h3.y;
                        acc[r * 16 + sc * 4 + 3] += w[r][jj * 4 + 2] * h3.z;
                        acc[r * 16 + sc * 4 + 3] += w[r][jj * 4 + 3] * h3.w;
                    }
                }
            }

            // butterfly 64 -> 2 per lane (indices 2*lane, 2*lane+1)
            red_round<16, 32>(acc, lane);
            red_round< 8, 16>(acc, lane);
            red_round< 4,  8>(acc, lane);
            red_round< 2,  4>(acc, lane);
            red_round< 1,  2>(acc, lane);

            const int t0o = 4 * k + c0;
            const size_t oi0 = (size_t)myN * TH + (size_t)t0o * HH + myRow;
            out[oi0]      = acc[0] + uv0;
            out[oi0 + HH] = acc[1] + uv1;
        }

        if (k == KSTEPS) break;              // no tail work needed

        __syncthreads();                     // all CTA stores issued
        if (tid == 0) st_release_gpu(myFlag, (unsigned)k);

        // ---- window A: ALL 4 u-GEMM sets for step k+1 (critical-path work
        //      that also covers the barrier release/skew)
        float uacc[64];
#pragma unroll
        for (int i = 0; i < 64; i++) uacc[i] = 0.0f;
        const float* xslot = xs + (k & 1) * XS_F;
        ugemm_set<0>(uacc, wp, xslot, lane);
        ugemm_set<1>(uacc, wp, xslot, lane);
        ugemm_set<2>(uacc, wp, xslot, lane);
        ugemm_set<3>(uacc, wp, xslot, lane);

        if (tid < GCTA) wait_ge(pollFlag, (unsigned)k);
        __syncthreads();

        // ---- post-poll: issue h LDGs first; stage_x + u-butterfly run in
        //      the LDG latency shadow; then STS h + sync.
        {
            const float4* src = reinterpret_cast<const float4*>(
                out + (size_t)sN * TH + (size_t)(4 * k + sC) * HH);
            float4* dst = reinterpret_cast<float4*>(&h_s[ss2 * HH]);

            float4 t0 = __ldcg(src + si);
            float4 t1 = __ldcg(src + si + 16);
            float4 t2 = __ldcg(src + si + 32);
            float4 t3 = __ldcg(src + si + 48);
            float4 t4 = __ldcg(src + si + 64);
            float4 t5 = __ldcg(src + si + 80);
            float4 t6 = __ldcg(src + si + 96);
            float4 t7 = __ldcg(src + si + 112);

            stage_x(xs + ((k + 1) & 1) * XS_F, x, n0, 4 * (k + 1), tid);
            ubutterfly(uacc, lane, btot, uv0, uv1);

            dst[si]       = t0;
            dst[si + 16]  = t1;
            dst[si + 32]  = t2;
            dst[si + 48]  = t3;
            dst[si + 64]  = t4;
            dst[si + 80]  = t5;
            dst[si + 96]  = t6;
            dst[si + 112] = t7;
        }
        __syncthreads();
    }
}

// ---------------------------------------------------------------------------
// Launch: inputs in metadata order: x, initial, W_ih, b_ih, W_hh
// 5 kernel launches + 1 D2D memcpy.
// ---------------------------------------------------------------------------
extern "C" void kernel_launch(void* const* d_in, const int* in_sizes, int n_in,
                              void* d_out, int out_size)
{
    const float* x       = (const float*)d_in[0];
    const float* initial = (const float*)d_in[1];
    const float* W_ih    = (const float*)d_in[2];
    const float* b_ih    = (const float*)d_in[3];
    const float* W_hh    = (const float*)d_in[4];
    float* out = (float*)d_out;
    const int dup = (out_size >= 2 * NTOT) ? 1 : 0;

    cudaFuncSetAttribute(rnn_kernel,
                         cudaFuncAttributeMaxDynamicSharedMemorySize, SMEM_BYTES);

    mm0_kernel<<<128, 512>>>(W_hh);                          // #1: W2 + WT
    mm1_kernel<<<dim3(64, 2), 512>>>(W_hh);                  // #2: W4, W3
    projw_kernel<<<dim3(HH, 3), 96>>>(W_hh, W_ih, b_ih);     // #3: Wp1..Wp3
    prologue_kernel<<<NB, 512>>>(x, initial, W_ih, b_ih, out);  // #4: h0..h3
    rnn_kernel<<<NCTA, 256, SMEM_BYTES>>>(out, x, W_ih, b_ih);  // #5: recurrence
    if (dup)
        cudaMemcpyAsync(out + NTOT, out, (size_t)NTOT * sizeof(float),
                        cudaMemcpyDeviceToDevice, 0);        // duplicate tensor
}